// round 8
// baseline (speedup 1.0000x reference)
#include <cuda_runtime.h>
#include <cuda_bf16.h>
#include <cstdint>

#define Nn   20000
#define NP   20096            // padded rows (157 * 128)
#define Ee   320000
#define DIN  128
#define Hh   512
#define NOUT 7
#define TOT  (Ee + Nn)
#define EPSL 1e-5f

// Wt layout: layer1 [512][128] then layers 2-4 [512][512] (hi and lo arrays)
#define WOFF1 0
#define WOFF2 65536
#define WOFF3 327680
#define WOFF4 589824
#define WTOT  851968

// ---- scratch (no allocs allowed: __device__ globals) ----
__device__ float g_h[(size_t)Nn * Hh];                  // GEMM output
__device__ __nv_bfloat16 g_a_hi[(size_t)NP * Hh];       // activations hi (padded)
__device__ __nv_bfloat16 g_a_lo[(size_t)NP * Hh];       // activations lo
__device__ float g_deg[Nn];
__device__ float g_dinv[Nn];
__device__ int   g_off[Nn + 1];
__device__ int   g_cur[Nn];
__device__ int   g_srcv[TOT];
__device__ float g_wv[TOT];
__device__ float g_pool[Hh];
__device__ __nv_bfloat16 g_wt_hi[WTOT];
__device__ __nv_bfloat16 g_wt_lo[WTOT];

// ================= helpers =================

__device__ __forceinline__ uint32_t smem_u32(const void* p) {
    uint32_t a;
    asm("{ .reg .u64 t; cvta.to.shared.u64 t, %1; cvt.u32.u64 %0, t; }" : "=r"(a) : "l"(p));
    return a;
}
__device__ __forceinline__ void ldsm_x4(uint32_t* r, uint32_t addr) {
    asm volatile("ldmatrix.sync.aligned.m8n8.x4.shared.b16 {%0,%1,%2,%3}, [%4];"
                 : "=r"(r[0]), "=r"(r[1]), "=r"(r[2]), "=r"(r[3]) : "r"(addr));
}
__device__ __forceinline__ void mma16816(float* d, const uint32_t* a, const uint32_t* b) {
    asm volatile("mma.sync.aligned.m16n8k16.row.col.f32.bf16.bf16.f32 "
                 "{%0,%1,%2,%3}, {%4,%5,%6,%7}, {%8,%9}, {%0,%1,%2,%3};"
                 : "+f"(d[0]), "+f"(d[1]), "+f"(d[2]), "+f"(d[3])
                 : "r"(a[0]), "r"(a[1]), "r"(a[2]), "r"(a[3]), "r"(b[0]), "r"(b[1]));
}
__device__ __forceinline__ void cp16(uint32_t dst, const void* src) {
    asm volatile("cp.async.ca.shared.global [%0], [%1], 16;" :: "r"(dst), "l"(src));
}
__device__ __forceinline__ void cp_commit() {
    asm volatile("cp.async.commit_group;" ::: "memory");
}
template <int N> __device__ __forceinline__ void cp_wait() {
    asm volatile("cp.async.wait_group %0;" :: "n"(N) : "memory");
}

static __device__ __forceinline__ void split2(float a, float b, unsigned& h, unsigned& l) {
    __nv_bfloat162 hh = __floats2bfloat162_rn(a, b);
    float ra = a - __bfloat162float(hh.x);
    float rb = b - __bfloat162float(hh.y);
    __nv_bfloat162 ll = __floats2bfloat162_rn(ra, rb);
    h = *(unsigned*)&hh;
    l = *(unsigned*)&ll;
}

// ================= graph preprocessing =================

__global__ void init_kernel() {
    int i = blockIdx.x * blockDim.x + threadIdx.x;
    if (i < Nn) { g_deg[i] = 0.f; g_cur[i] = 0; }
    if (i < Hh) g_pool[i] = 0.f;
}

__global__ void deg_kernel(const int* __restrict__ ei) {
    int i = blockIdx.x * blockDim.x + threadIdx.x;
    if (i < Ee) atomicAdd(&g_deg[ei[Ee + i]], 1.0f);
}

// warp-shuffle based scan (+ fused dinv), 1024 threads
__global__ void scan_kernel() {
    __shared__ int wsum[32];
    __shared__ int carry;
    int t = threadIdx.x, lane = t & 31, w = t >> 5;
    if (t == 0) { carry = 0; g_off[0] = 0; }
    __syncthreads();
    for (int base = 0; base < Nn; base += 1024) {
        int i = base + t;
        int v = 0;
        if (i < Nn) {
            v = (int)g_deg[i] + 1;
            g_dinv[i] = rsqrtf((float)v);
        }
        int s = v;
#pragma unroll
        for (int o = 1; o < 32; o <<= 1) {
            int u = __shfl_up_sync(0xffffffffu, s, o);
            if (lane >= o) s += u;
        }
        if (lane == 31) wsum[w] = s;
        __syncthreads();
        if (w == 0) {
            int ws = wsum[lane];
#pragma unroll
            for (int o = 1; o < 32; o <<= 1) {
                int u = __shfl_up_sync(0xffffffffu, ws, o);
                if (lane >= o) ws += u;
            }
            wsum[lane] = ws;
        }
        __syncthreads();
        int boff = (w ? wsum[w - 1] : 0);
        if (i < Nn) g_off[i + 1] = carry + boff + s;
        __syncthreads();
        if (t == 0) carry += wsum[31];
        __syncthreads();
    }
}

__global__ void fill_kernel(const int* __restrict__ ei) {
    int i = blockIdx.x * blockDim.x + threadIdx.x;
    if (i >= TOT) return;
    int s, d;
    if (i < Ee) { s = ei[i]; d = ei[Ee + i]; }
    else        { s = i - Ee; d = s; }
    int pos = atomicAdd(&g_cur[d], 1);
    int idx = g_off[d] + pos;
    g_srcv[idx] = s;
    g_wv[idx]   = g_dinv[s] * g_dinv[d];
}

// ============== all-layer weight transpose + bf16 hi/lo split ==============

__global__ void wt_all_kernel(const float* __restrict__ W1, const float* __restrict__ W2,
                              const float* __restrict__ W3, const float* __restrict__ W4) {
    int idx = blockIdx.x * blockDim.x + threadIdx.x;
    if (idx >= WTOT) return;
    const float* W; int K, loc;
    if (idx < WOFF2)      { W = W1; K = DIN; loc = idx; }
    else if (idx < WOFF3) { W = W2; K = Hh;  loc = idx - WOFF2; }
    else if (idx < WOFF4) { W = W3; K = Hh;  loc = idx - WOFF3; }
    else                  { W = W4; K = Hh;  loc = idx - WOFF4; }
    int n = loc / K, k = loc % K;          // output index [n][k]
    float a = W[(size_t)k * Hh + n];       // source [k][n]
    __nv_bfloat16 h = __float2bfloat16(a);
    g_wt_hi[idx] = h;
    g_wt_lo[idx] = __float2bfloat16(a - __bfloat162float(h));
}

// ============== layer-1 input conversion: x fp32 -> hi/lo bf16 ==============

__global__ void cvt_kernel(const float* __restrict__ x) {
    int i = blockIdx.x * blockDim.x + threadIdx.x;
    if (i >= Nn * DIN / 2) return;
    float2 v = *(const float2*)&x[i * 2];
    unsigned h, l;
    split2(v.x, v.y, h, l);
    *(unsigned*)&g_a_hi[i * 2] = h;
    *(unsigned*)&g_a_lo[i * 2] = l;
}

// ============ warp-MMA bf16 GEMM, 3-stage cp.async, SW64 swizzle ============
// C[N,512] = A[N,K] @ W[K,512]; A pre-split hi/lo, W^T pre-split.
// CTA: 128x128 tile, 256 threads, 8 warps (4m x 2n), warp tile 32x64, BK=32.
// Rows 64 B with XOR swizzle (16B chunk c ^= (r>>1)&3). One barrier per chunk.

#define BM 128
#define BN 128
#define ARR_B 8192               // bytes per array per stage (128 rows x 64 B)
#define STG_B (4 * ARR_B)        // 32768 per stage
#define GEMM_SMEM (3 * STG_B)    // 98304

__global__ void __launch_bounds__(256, 2)
mma_gemm(int K, int woff) {
    extern __shared__ __align__(16) char dynsmem[];
    const uint32_t sb = smem_u32(dynsmem);

    const int t    = threadIdx.x;
    const int lane = t & 31;
    const int wid  = t >> 5;
    const int wm   = (wid & 3) * 32;
    const int wn   = (wid >> 2) * 64;
    const int m0   = blockIdx.y * BM;
    const int n0   = blockIdx.x * BN;

    const __nv_bfloat16* srcp[4] = {
        g_a_hi + (size_t)m0 * K, g_a_lo + (size_t)m0 * K,
        g_wt_hi + woff + (size_t)n0 * K, g_wt_lo + woff + (size_t)n0 * K
    };

    float acc[2][8][4];
#pragma unroll
    for (int i = 0; i < 2; i++)
#pragma unroll
        for (int j = 0; j < 8; j++)
#pragma unroll
            for (int k = 0; k < 4; k++) acc[i][j][k] = 0.f;

    const int nch = K >> 5;

    // cp.async issue of chunk c into stage c%3: 2048 16B segs, 8 per thread
    auto issue = [&](int c) {
        const uint32_t stb = sb + (uint32_t)(c % 3) * STG_B;
        const int k0 = c << 5;
#pragma unroll
        for (int i = 0; i < 8; i++) {
            int seg = t + i * 256;
            int arr = seg >> 9;
            int rem = seg & 511;
            int r   = rem >> 2;
            int sgi = rem & 3;
            uint32_t dst = stb + (uint32_t)(arr * ARR_B + r * 64 +
                                            ((sgi ^ ((r >> 1) & 3)) << 4));
            cp16(dst, srcp[arr] + (size_t)r * K + k0 + sgi * 8);
        }
        cp_commit();
    };

    // ldmatrix lane mapping
    const int arow = lane & 15, acolg = lane >> 4;
    const int brow = (lane & 7) + ((lane >> 4) << 3);
    const int bcolg = (lane >> 3) & 1;

    issue(0);
    issue(1);

    for (int c = 0; c < nch; c++) {
        if (c + 1 < nch) cp_wait<1>();   // chunk c complete, chunk c+1 may be in flight
        else             cp_wait<0>();   // last chunk: drain everything
        __syncthreads();                 // also guards stage (c+2)%3 reuse below

        if (c + 2 < nch) issue(c + 2);

        const uint32_t stb = sb + (uint32_t)(c % 3) * STG_B;
        const uint32_t aH = stb;
        const uint32_t aL = stb + ARR_B;
        const uint32_t bH = stb + 2 * ARR_B;
        const uint32_t bL = stb + 3 * ARR_B;

#pragma unroll
        for (int ks = 0; ks < 2; ks++) {
            uint32_t ah[2][4], al[2][4];
#pragma unroll
            for (int mt = 0; mt < 2; mt++) {
                int rr = wm + mt * 16 + arow;
                uint32_t off = (uint32_t)(rr * 64 +
                               (((2 * ks + acolg) ^ ((rr >> 1) & 3)) << 4));
                ldsm_x4(ah[mt], aH + off);
                ldsm_x4(al[mt], aL + off);
            }
#pragma unroll
            for (int np = 0; np < 4; np++) {
                int rr = wn + np * 16 + brow;
                uint32_t boff = (uint32_t)(rr * 64 +
                                (((2 * ks + bcolg) ^ ((rr >> 1) & 3)) << 4));
                uint32_t bh[4], bl[4];
                ldsm_x4(bh, bH + boff);
                ldsm_x4(bl, bL + boff);
#pragma unroll
                for (int mt = 0; mt < 2; mt++) {
                    mma16816(acc[mt][np * 2 + 0], ah[mt], bh + 0);
                    mma16816(acc[mt][np * 2 + 1], ah[mt], bh + 2);
                    mma16816(acc[mt][np * 2 + 0], ah[mt], bl + 0);
                    mma16816(acc[mt][np * 2 + 1], ah[mt], bl + 2);
                    mma16816(acc[mt][np * 2 + 0], al[mt], bh + 0);
                    mma16816(acc[mt][np * 2 + 1], al[mt], bh + 2);
                }
            }
        }
    }

    // ---- epilogue: acc -> g_h (fp32) ----
    const int quad = lane >> 2;
    const int qi   = lane & 3;
#pragma unroll
    for (int mt = 0; mt < 2; mt++) {
        int r0 = m0 + wm + mt * 16 + quad;
#pragma unroll
        for (int nt = 0; nt < 8; nt++) {
            int cc = n0 + wn + nt * 8 + qi * 2;
            if (r0 < Nn)
                *(float2*)&g_h[(size_t)r0 * Hh + cc] = make_float2(acc[mt][nt][0], acc[mt][nt][1]);
            if (r0 + 8 < Nn)
                *(float2*)&g_h[(size_t)(r0 + 8) * Hh + cc] = make_float2(acc[mt][nt][2], acc[mt][nt][3]);
        }
    }
}

// ======= fused CSR gather-aggregate + bias + LayerNorm + ReLU =======
// output written as pre-split hi/lo bf16 for the next GEMM / pool

__global__ void __launch_bounds__(128)
agg_kernel(const float* __restrict__ bias,
           const float* __restrict__ gamma,
           const float* __restrict__ beta) {
    const int n = blockIdx.x;
    const int t = threadIdx.x;
    const int beg = g_off[n], end = g_off[n + 1];
    const int fo = t * 4;

    float4 acc = make_float4(0.f, 0.f, 0.f, 0.f);
#pragma unroll 2
    for (int j = beg; j < end; j++) {
        int   s = g_srcv[j];
        float wv = g_wv[j];
        float4 v = *(const float4*)&g_h[(size_t)s * Hh + fo];
        acc.x = fmaf(wv, v.x, acc.x);
        acc.y = fmaf(wv, v.y, acc.y);
        acc.z = fmaf(wv, v.z, acc.z);
        acc.w = fmaf(wv, v.w, acc.w);
    }
    float4 b = *(const float4*)&bias[fo];
    acc.x += b.x; acc.y += b.y; acc.z += b.z; acc.w += b.w;

    float s1 = acc.x + acc.y + acc.z + acc.w;
    float s2 = acc.x * acc.x + acc.y * acc.y + acc.z * acc.z + acc.w * acc.w;
#pragma unroll
    for (int o = 16; o > 0; o >>= 1) {
        s1 += __shfl_xor_sync(0xffffffffu, s1, o);
        s2 += __shfl_xor_sync(0xffffffffu, s2, o);
    }
    __shared__ float sm1[4], sm2[4];
    if ((t & 31) == 0) { sm1[t >> 5] = s1; sm2[t >> 5] = s2; }
    __syncthreads();
    float S1 = sm1[0] + sm1[1] + sm1[2] + sm1[3];
    float S2 = sm2[0] + sm2[1] + sm2[2] + sm2[3];
    float mu  = S1 * (1.0f / Hh);
    float var = S2 * (1.0f / Hh) - mu * mu;
    float inv = rsqrtf(var + EPSL);

    float4 gm = *(const float4*)&gamma[fo];
    float4 bt = *(const float4*)&beta[fo];
    float4 y;
    y.x = fmaxf((acc.x - mu) * inv * gm.x + bt.x, 0.f);
    y.y = fmaxf((acc.y - mu) * inv * gm.y + bt.y, 0.f);
    y.z = fmaxf((acc.z - mu) * inv * gm.z + bt.z, 0.f);
    y.w = fmaxf((acc.w - mu) * inv * gm.w + bt.w, 0.f);

    uint2 hv, lv;
    split2(y.x, y.y, hv.x, lv.x);
    split2(y.z, y.w, hv.y, lv.y);
    *(uint2*)&g_a_hi[(size_t)n * Hh + fo] = hv;
    *(uint2*)&g_a_lo[(size_t)n * Hh + fo] = lv;
}

// ================= mean pool + output projection =================

__global__ void pool_kernel() {
    int f = threadIdx.x;
    float s = 0.f;
    for (int n = blockIdx.x; n < Nn; n += gridDim.x) {
        size_t idx = (size_t)n * Hh + f;
        s += __bfloat162float(g_a_hi[idx]) + __bfloat162float(g_a_lo[idx]);
    }
    atomicAdd(&g_pool[f], s);
}

__global__ void out_kernel(const float* __restrict__ Wout,
                           const float* __restrict__ bout,
                           float* __restrict__ out) {
    __shared__ float sm[NOUT][256];
    int t = threadIdx.x;
    float acc[NOUT];
#pragma unroll
    for (int o = 0; o < NOUT; o++) acc[o] = 0.f;
    for (int f = t; f < Hh; f += 256) {
        float p = g_pool[f] * (1.0f / Nn);
#pragma unroll
        for (int o = 0; o < NOUT; o++)
            acc[o] = fmaf(p, Wout[f * NOUT + o], acc[o]);
    }
#pragma unroll
    for (int o = 0; o < NOUT; o++) sm[o][t] = acc[o];
    __syncthreads();
    for (int st = 128; st > 0; st >>= 1) {
        if (t < st) {
#pragma unroll
            for (int o = 0; o < NOUT; o++) sm[o][t] += sm[o][t + st];
        }
        __syncthreads();
    }
    if (t < NOUT) out[t] = sm[t][0] + bout[t];
}

// ================= launch =================

extern "C" void kernel_launch(void* const* d_in, const int* in_sizes, int n_in,
                              void* d_out, int out_size) {
    const float* x  = (const float*)d_in[0];
    const int*   ei = (const int*)d_in[1];
    const float* W1 = (const float*)d_in[2];  const float* b1 = (const float*)d_in[3];
    const float* W2 = (const float*)d_in[4];  const float* b2 = (const float*)d_in[5];
    const float* W3 = (const float*)d_in[6];  const float* b3 = (const float*)d_in[7];
    const float* W4 = (const float*)d_in[8];  const float* b4 = (const float*)d_in[9];
    const float* gm = (const float*)d_in[10]; const float* bt = (const float*)d_in[11];
    const float* Wo = (const float*)d_in[12]; const float* bo = (const float*)d_in[13];
    float* out = (float*)d_out;

    cudaFuncSetAttribute(mma_gemm, cudaFuncAttributeMaxDynamicSharedMemorySize, GEMM_SMEM);

    init_kernel<<<(Nn + 255) / 256, 256>>>();
    deg_kernel<<<(Ee + 255) / 256, 256>>>(ei);
    wt_all_kernel<<<(WTOT + 255) / 256, 256>>>(W1, W2, W3, W4);
    cvt_kernel<<<(Nn * DIN / 2 + 255) / 256, 256>>>(x);
    scan_kernel<<<1, 1024>>>();
    fill_kernel<<<(TOT + 255) / 256, 256>>>(ei);

    dim3 ggrid(Hh / BN, NP / BM);   // (4, 157)

    mma_gemm<<<ggrid, 256, GEMM_SMEM>>>(DIN, WOFF1);
    agg_kernel<<<Nn, 128>>>(b1, gm, bt);
    mma_gemm<<<ggrid, 256, GEMM_SMEM>>>(Hh, WOFF2);
    agg_kernel<<<Nn, 128>>>(b2, gm, bt);
    mma_gemm<<<ggrid, 256, GEMM_SMEM>>>(Hh, WOFF3);
    agg_kernel<<<Nn, 128>>>(b3, gm, bt);
    mma_gemm<<<ggrid, 256, GEMM_SMEM>>>(Hh, WOFF4);
    agg_kernel<<<Nn, 128>>>(b4, gm, bt);

    pool_kernel<<<148, 512>>>();
    out_kernel<<<1, 256>>>(Wo, bo, out);
}

// round 9
// speedup vs baseline: 1.0615x; 1.0615x over previous
#include <cuda_runtime.h>
#include <cuda_bf16.h>
#include <cstdint>

#define Nn   20000
#define NP   20096            // padded rows (157 * 128)
#define Ee   320000
#define DIN  128
#define Hh   512
#define NOUT 7
#define TOT  (Ee + Nn)
#define EPSL 1e-5f

// Wt layout: layer1 [512][128] then layers 2-4 [512][512] (hi and lo arrays)
#define WOFF1 0
#define WOFF2 65536
#define WOFF3 327680
#define WOFF4 589824
#define WTOT  851968

// ---- scratch (no allocs allowed: __device__ globals) ----
__device__ __nv_bfloat16 g_h[(size_t)Nn * Hh];          // GEMM output (bf16!)
__device__ __nv_bfloat16 g_a_hi[(size_t)NP * Hh];       // activations hi (padded)
__device__ __nv_bfloat16 g_a_lo[(size_t)NP * Hh];       // activations lo
__device__ float g_deg[Nn];
__device__ float g_dinv[Nn];
__device__ int   g_off[Nn + 1];
__device__ int   g_cur[Nn];
__device__ int   g_srcv[TOT];
__device__ float g_wv[TOT];
__device__ float g_pool[Hh];
__device__ __nv_bfloat16 g_wt_hi[WTOT];
__device__ __nv_bfloat16 g_wt_lo[WTOT];

// ================= helpers =================

__device__ __forceinline__ uint32_t smem_u32(const void* p) {
    uint32_t a;
    asm("{ .reg .u64 t; cvta.to.shared.u64 t, %1; cvt.u32.u64 %0, t; }" : "=r"(a) : "l"(p));
    return a;
}
__device__ __forceinline__ void ldsm_x4(uint32_t* r, uint32_t addr) {
    asm volatile("ldmatrix.sync.aligned.m8n8.x4.shared.b16 {%0,%1,%2,%3}, [%4];"
                 : "=r"(r[0]), "=r"(r[1]), "=r"(r[2]), "=r"(r[3]) : "r"(addr));
}
__device__ __forceinline__ void mma16816(float* d, const uint32_t* a, const uint32_t* b) {
    asm volatile("mma.sync.aligned.m16n8k16.row.col.f32.bf16.bf16.f32 "
                 "{%0,%1,%2,%3}, {%4,%5,%6,%7}, {%8,%9}, {%0,%1,%2,%3};"
                 : "+f"(d[0]), "+f"(d[1]), "+f"(d[2]), "+f"(d[3])
                 : "r"(a[0]), "r"(a[1]), "r"(a[2]), "r"(a[3]), "r"(b[0]), "r"(b[1]));
}
__device__ __forceinline__ void cp16(uint32_t dst, const void* src) {
    asm volatile("cp.async.ca.shared.global [%0], [%1], 16;" :: "r"(dst), "l"(src));
}
__device__ __forceinline__ void cp_commit() {
    asm volatile("cp.async.commit_group;" ::: "memory");
}
template <int N> __device__ __forceinline__ void cp_wait() {
    asm volatile("cp.async.wait_group %0;" :: "n"(N) : "memory");
}

static __device__ __forceinline__ void split2(float a, float b, unsigned& h, unsigned& l) {
    __nv_bfloat162 hh = __floats2bfloat162_rn(a, b);
    float ra = a - __bfloat162float(hh.x);
    float rb = b - __bfloat162float(hh.y);
    __nv_bfloat162 ll = __floats2bfloat162_rn(ra, rb);
    h = *(unsigned*)&hh;
    l = *(unsigned*)&ll;
}

// ================= graph preprocessing =================

__global__ void init_kernel() {
    int i = blockIdx.x * blockDim.x + threadIdx.x;
    if (i < Nn) { g_deg[i] = 0.f; g_cur[i] = 0; }
    if (i < Hh) g_pool[i] = 0.f;
}

__global__ void deg_kernel(const int* __restrict__ ei) {
    int i = blockIdx.x * blockDim.x + threadIdx.x;
    if (i < Ee) atomicAdd(&g_deg[ei[Ee + i]], 1.0f);
}

// warp-shuffle based scan (+ fused dinv), 1024 threads
__global__ void scan_kernel() {
    __shared__ int wsum[32];
    __shared__ int carry;
    int t = threadIdx.x, lane = t & 31, w = t >> 5;
    if (t == 0) { carry = 0; g_off[0] = 0; }
    __syncthreads();
    for (int base = 0; base < Nn; base += 1024) {
        int i = base + t;
        int v = 0;
        if (i < Nn) {
            v = (int)g_deg[i] + 1;
            g_dinv[i] = rsqrtf((float)v);
        }
        int s = v;
#pragma unroll
        for (int o = 1; o < 32; o <<= 1) {
            int u = __shfl_up_sync(0xffffffffu, s, o);
            if (lane >= o) s += u;
        }
        if (lane == 31) wsum[w] = s;
        __syncthreads();
        if (w == 0) {
            int ws = wsum[lane];
#pragma unroll
            for (int o = 1; o < 32; o <<= 1) {
                int u = __shfl_up_sync(0xffffffffu, ws, o);
                if (lane >= o) ws += u;
            }
            wsum[lane] = ws;
        }
        __syncthreads();
        int boff = (w ? wsum[w - 1] : 0);
        if (i < Nn) g_off[i + 1] = carry + boff + s;
        __syncthreads();
        if (t == 0) carry += wsum[31];
        __syncthreads();
    }
}

__global__ void fill_kernel(const int* __restrict__ ei) {
    int i = blockIdx.x * blockDim.x + threadIdx.x;
    if (i >= TOT) return;
    int s, d;
    if (i < Ee) { s = ei[i]; d = ei[Ee + i]; }
    else        { s = i - Ee; d = s; }
    int pos = atomicAdd(&g_cur[d], 1);
    int idx = g_off[d] + pos;
    g_srcv[idx] = s;
    g_wv[idx]   = g_dinv[s] * g_dinv[d];
}

// ==== fused: weight transpose + hi/lo split AND layer-1 input conversion ====

#define CVT_ITEMS (Nn * DIN / 2)

__global__ void wt_cvt_kernel(const float* __restrict__ W1, const float* __restrict__ W2,
                              const float* __restrict__ W3, const float* __restrict__ W4,
                              const float* __restrict__ x) {
    int idx = blockIdx.x * blockDim.x + threadIdx.x;
    if (idx < WTOT) {
        const float* W; int K, loc;
        if (idx < WOFF2)      { W = W1; K = DIN; loc = idx; }
        else if (idx < WOFF3) { W = W2; K = Hh;  loc = idx - WOFF2; }
        else if (idx < WOFF4) { W = W3; K = Hh;  loc = idx - WOFF3; }
        else                  { W = W4; K = Hh;  loc = idx - WOFF4; }
        int n = loc / K, k = loc % K;          // output index [n][k]
        float a = W[(size_t)k * Hh + n];       // source [k][n]
        __nv_bfloat16 h = __float2bfloat16(a);
        g_wt_hi[idx] = h;
        g_wt_lo[idx] = __float2bfloat16(a - __bfloat162float(h));
    } else {
        int i = idx - WTOT;
        if (i >= CVT_ITEMS) return;
        float2 v = *(const float2*)&x[i * 2];
        unsigned h, l;
        split2(v.x, v.y, h, l);
        *(unsigned*)&g_a_hi[i * 2] = h;
        *(unsigned*)&g_a_lo[i * 2] = l;
    }
}

// ============ warp-MMA bf16 GEMM, 2-stage cp.async, SW64 swizzle ============
// C[N,512] = A[N,K] @ W[K,512]; A pre-split hi/lo, W^T pre-split.
// CTA: 128x128 tile, 256 threads, 8 warps (4m x 2n), warp tile 32x64, BK=32.
// Rows 64 B, XOR swizzle (16B chunk c ^= (r>>1)&3). Output g_h in bf16.

#define BM 128
#define BN 128
#define ARR_B 8192               // bytes per array per stage (128 rows x 64 B)
#define STG_B (4 * ARR_B)        // 32768 per stage
#define GEMM_SMEM (2 * STG_B)    // 65536

__global__ void __launch_bounds__(256, 2)
mma_gemm(int K, int woff) {
    extern __shared__ __align__(16) char dynsmem[];
    const uint32_t sb = smem_u32(dynsmem);

    const int t    = threadIdx.x;
    const int lane = t & 31;
    const int wid  = t >> 5;
    const int wm   = (wid & 3) * 32;
    const int wn   = (wid >> 2) * 64;
    const int m0   = blockIdx.y * BM;
    const int n0   = blockIdx.x * BN;

    const __nv_bfloat16* srcp[4] = {
        g_a_hi + (size_t)m0 * K, g_a_lo + (size_t)m0 * K,
        g_wt_hi + woff + (size_t)n0 * K, g_wt_lo + woff + (size_t)n0 * K
    };

    float acc[2][8][4];
#pragma unroll
    for (int i = 0; i < 2; i++)
#pragma unroll
        for (int j = 0; j < 8; j++)
#pragma unroll
            for (int k = 0; k < 4; k++) acc[i][j][k] = 0.f;

    const int nch = K >> 5;

    // cp.async issue of chunk c into stage c%2: 2048 16B segs, 8 per thread
    auto issue = [&](int c) {
        const uint32_t stb = sb + (uint32_t)(c & 1) * STG_B;
        const int k0 = c << 5;
#pragma unroll
        for (int i = 0; i < 8; i++) {
            int seg = t + i * 256;
            int arr = seg >> 9;
            int rem = seg & 511;
            int r   = rem >> 2;
            int sgi = rem & 3;
            uint32_t dst = stb + (uint32_t)(arr * ARR_B + r * 64 +
                                            ((sgi ^ ((r >> 1) & 3)) << 4));
            cp16(dst, srcp[arr] + (size_t)r * K + k0 + sgi * 8);
        }
        cp_commit();
    };

    // ldmatrix lane mapping
    const int arow = lane & 15, acolg = lane >> 4;
    const int brow = (lane & 7) + ((lane >> 4) << 3);
    const int bcolg = (lane >> 3) & 1;

    issue(0);

    for (int c = 0; c < nch; c++) {
        if (c + 1 < nch) { issue(c + 1); cp_wait<1>(); }
        else             { cp_wait<0>(); }
        __syncthreads();

        const uint32_t stb = sb + (uint32_t)(c & 1) * STG_B;
        const uint32_t aH = stb;
        const uint32_t aL = stb + ARR_B;
        const uint32_t bH = stb + 2 * ARR_B;
        const uint32_t bL = stb + 3 * ARR_B;

#pragma unroll
        for (int ks = 0; ks < 2; ks++) {
            uint32_t ah[2][4], al[2][4];
#pragma unroll
            for (int mt = 0; mt < 2; mt++) {
                int rr = wm + mt * 16 + arow;
                uint32_t off = (uint32_t)(rr * 64 +
                               (((2 * ks + acolg) ^ ((rr >> 1) & 3)) << 4));
                ldsm_x4(ah[mt], aH + off);
                ldsm_x4(al[mt], aL + off);
            }
#pragma unroll
            for (int np = 0; np < 4; np++) {
                int rr = wn + np * 16 + brow;
                uint32_t boff = (uint32_t)(rr * 64 +
                                (((2 * ks + bcolg) ^ ((rr >> 1) & 3)) << 4));
                uint32_t bh[4], bl[4];
                ldsm_x4(bh, bH + boff);
                ldsm_x4(bl, bL + boff);
#pragma unroll
                for (int mt = 0; mt < 2; mt++) {
                    mma16816(acc[mt][np * 2 + 0], ah[mt], bh + 0);
                    mma16816(acc[mt][np * 2 + 1], ah[mt], bh + 2);
                    mma16816(acc[mt][np * 2 + 0], ah[mt], bl + 0);
                    mma16816(acc[mt][np * 2 + 1], ah[mt], bl + 2);
                    mma16816(acc[mt][np * 2 + 0], al[mt], bh + 0);
                    mma16816(acc[mt][np * 2 + 1], al[mt], bh + 2);
                }
            }
        }
        __syncthreads();   // stage reuse guard
    }

    // ---- epilogue: acc -> g_h (bf16) ----
    const int quad = lane >> 2;
    const int qi   = lane & 3;
#pragma unroll
    for (int mt = 0; mt < 2; mt++) {
        int r0 = m0 + wm + mt * 16 + quad;
#pragma unroll
        for (int nt = 0; nt < 8; nt++) {
            int cc = n0 + wn + nt * 8 + qi * 2;
            if (r0 < Nn) {
                __nv_bfloat162 v = __floats2bfloat162_rn(acc[mt][nt][0], acc[mt][nt][1]);
                *(__nv_bfloat162*)&g_h[(size_t)r0 * Hh + cc] = v;
            }
            if (r0 + 8 < Nn) {
                __nv_bfloat162 v = __floats2bfloat162_rn(acc[mt][nt][2], acc[mt][nt][3]);
                *(__nv_bfloat162*)&g_h[(size_t)(r0 + 8) * Hh + cc] = v;
            }
        }
    }
}

// ======= fused CSR gather-aggregate + bias + LayerNorm + ReLU =======
// reads bf16 messages (half traffic); writes pre-split hi/lo bf16 activations

__global__ void __launch_bounds__(128)
agg_kernel(const float* __restrict__ bias,
           const float* __restrict__ gamma,
           const float* __restrict__ beta) {
    const int n = blockIdx.x;
    const int t = threadIdx.x;
    const int beg = g_off[n], end = g_off[n + 1];
    const int fo = t * 4;

    float4 acc = make_float4(0.f, 0.f, 0.f, 0.f);
#pragma unroll 2
    for (int j = beg; j < end; j++) {
        int   s = g_srcv[j];
        float wv = g_wv[j];
        uint2 rv = *(const uint2*)&g_h[(size_t)s * Hh + fo];
        float2 f0 = __bfloat1622float2(*(__nv_bfloat162*)&rv.x);
        float2 f1 = __bfloat1622float2(*(__nv_bfloat162*)&rv.y);
        acc.x = fmaf(wv, f0.x, acc.x);
        acc.y = fmaf(wv, f0.y, acc.y);
        acc.z = fmaf(wv, f1.x, acc.z);
        acc.w = fmaf(wv, f1.y, acc.w);
    }
    float4 b = *(const float4*)&bias[fo];
    acc.x += b.x; acc.y += b.y; acc.z += b.z; acc.w += b.w;

    float s1 = acc.x + acc.y + acc.z + acc.w;
    float s2 = acc.x * acc.x + acc.y * acc.y + acc.z * acc.z + acc.w * acc.w;
#pragma unroll
    for (int o = 16; o > 0; o >>= 1) {
        s1 += __shfl_xor_sync(0xffffffffu, s1, o);
        s2 += __shfl_xor_sync(0xffffffffu, s2, o);
    }
    __shared__ float sm1[4], sm2[4];
    if ((t & 31) == 0) { sm1[t >> 5] = s1; sm2[t >> 5] = s2; }
    __syncthreads();
    float S1 = sm1[0] + sm1[1] + sm1[2] + sm1[3];
    float S2 = sm2[0] + sm2[1] + sm2[2] + sm2[3];
    float mu  = S1 * (1.0f / Hh);
    float var = S2 * (1.0f / Hh) - mu * mu;
    float inv = rsqrtf(var + EPSL);

    float4 gm = *(const float4*)&gamma[fo];
    float4 bt = *(const float4*)&beta[fo];
    float4 y;
    y.x = fmaxf((acc.x - mu) * inv * gm.x + bt.x, 0.f);
    y.y = fmaxf((acc.y - mu) * inv * gm.y + bt.y, 0.f);
    y.z = fmaxf((acc.z - mu) * inv * gm.z + bt.z, 0.f);
    y.w = fmaxf((acc.w - mu) * inv * gm.w + bt.w, 0.f);

    uint2 hv, lv;
    split2(y.x, y.y, hv.x, lv.x);
    split2(y.z, y.w, hv.y, lv.y);
    *(uint2*)&g_a_hi[(size_t)n * Hh + fo] = hv;
    *(uint2*)&g_a_lo[(size_t)n * Hh + fo] = lv;
}

// ================= mean pool + output projection =================

__global__ void pool_kernel() {
    int f = threadIdx.x;
    float s = 0.f;
    for (int n = blockIdx.x; n < Nn; n += gridDim.x) {
        size_t idx = (size_t)n * Hh + f;
        s += __bfloat162float(g_a_hi[idx]) + __bfloat162float(g_a_lo[idx]);
    }
    atomicAdd(&g_pool[f], s);
}

__global__ void out_kernel(const float* __restrict__ Wout,
                           const float* __restrict__ bout,
                           float* __restrict__ out) {
    __shared__ float sm[NOUT][256];
    int t = threadIdx.x;
    float acc[NOUT];
#pragma unroll
    for (int o = 0; o < NOUT; o++) acc[o] = 0.f;
    for (int f = t; f < Hh; f += 256) {
        float p = g_pool[f] * (1.0f / Nn);
#pragma unroll
        for (int o = 0; o < NOUT; o++)
            acc[o] = fmaf(p, Wout[f * NOUT + o], acc[o]);
    }
#pragma unroll
    for (int o = 0; o < NOUT; o++) sm[o][t] = acc[o];
    __syncthreads();
    for (int st = 128; st > 0; st >>= 1) {
        if (t < st) {
#pragma unroll
            for (int o = 0; o < NOUT; o++) sm[o][t] += sm[o][t + st];
        }
        __syncthreads();
    }
    if (t < NOUT) out[t] = sm[t][0] + bout[t];
}

// ================= launch =================

extern "C" void kernel_launch(void* const* d_in, const int* in_sizes, int n_in,
                              void* d_out, int out_size) {
    const float* x  = (const float*)d_in[0];
    const int*   ei = (const int*)d_in[1];
    const float* W1 = (const float*)d_in[2];  const float* b1 = (const float*)d_in[3];
    const float* W2 = (const float*)d_in[4];  const float* b2 = (const float*)d_in[5];
    const float* W3 = (const float*)d_in[6];  const float* b3 = (const float*)d_in[7];
    const float* W4 = (const float*)d_in[8];  const float* b4 = (const float*)d_in[9];
    const float* gm = (const float*)d_in[10]; const float* bt = (const float*)d_in[11];
    const float* Wo = (const float*)d_in[12]; const float* bo = (const float*)d_in[13];
    float* out = (float*)d_out;

    cudaFuncSetAttribute(mma_gemm, cudaFuncAttributeMaxDynamicSharedMemorySize, GEMM_SMEM);

    // launch order chosen so index 5 (ncu -s 5 -c 1) = first mma_gemm
    init_kernel<<<(Nn + 255) / 256, 256>>>();                                   // 0
    deg_kernel<<<(Ee + 255) / 256, 256>>>(ei);                                  // 1
    scan_kernel<<<1, 1024>>>();                                                 // 2
    fill_kernel<<<(TOT + 255) / 256, 256>>>(ei);                                // 3
    wt_cvt_kernel<<<(WTOT + CVT_ITEMS + 255) / 256, 256>>>(W1, W2, W3, W4, x);  // 4

    dim3 ggrid(Hh / BN, NP / BM);   // (4, 157)

    mma_gemm<<<ggrid, 256, GEMM_SMEM>>>(DIN, WOFF1);                            // 5 (profiled)
    agg_kernel<<<Nn, 128>>>(b1, gm, bt);
    mma_gemm<<<ggrid, 256, GEMM_SMEM>>>(Hh, WOFF2);
    agg_kernel<<<Nn, 128>>>(b2, gm, bt);
    mma_gemm<<<ggrid, 256, GEMM_SMEM>>>(Hh, WOFF3);
    agg_kernel<<<Nn, 128>>>(b3, gm, bt);
    mma_gemm<<<ggrid, 256, GEMM_SMEM>>>(Hh, WOFF4);
    agg_kernel<<<Nn, 128>>>(b4, gm, bt);

    pool_kernel<<<148, 512>>>();
    out_kernel<<<1, 256>>>(Wo, bo, out);
}

// round 10
// speedup vs baseline: 1.2637x; 1.1905x over previous
#include <cuda_runtime.h>
#include <cuda_bf16.h>
#include <cstdint>

#define Nn   20000
#define NP   20096            // padded rows (157 * 128)
#define Ee   320000
#define DIN  128
#define Hh   512
#define NOUT 7
#define TOT  (Ee + Nn)
#define EPSL 1e-5f

// Wt layout: layer1 [512][128] then layers 2-4 [512][512] (hi and lo arrays)
#define WOFF1 0
#define WOFF2 65536
#define WOFF3 327680
#define WOFF4 589824
#define WTOT  851968

// ---- scratch (no allocs allowed: __device__ globals) ----
__device__ __nv_bfloat16 g_h[(size_t)Nn * Hh];          // GEMM output (bf16)
__device__ __nv_bfloat16 g_a[(size_t)NP * Hh];          // activations (bf16, padded)
__device__ float g_deg[Nn];
__device__ float g_dinv[Nn];
__device__ int   g_off[Nn + 1];
__device__ int   g_cur[Nn];
__device__ int   g_srcv[TOT];
__device__ float g_wv[TOT];
__device__ float g_pool[Hh];
__device__ __nv_bfloat16 g_wt_hi[WTOT];
__device__ __nv_bfloat16 g_wt_lo[WTOT];

// ================= helpers =================

__device__ __forceinline__ uint32_t smem_u32(const void* p) {
    uint32_t a;
    asm("{ .reg .u64 t; cvta.to.shared.u64 t, %1; cvt.u32.u64 %0, t; }" : "=r"(a) : "l"(p));
    return a;
}
__device__ __forceinline__ void ldsm_x4(uint32_t* r, uint32_t addr) {
    asm volatile("ldmatrix.sync.aligned.m8n8.x4.shared.b16 {%0,%1,%2,%3}, [%4];"
                 : "=r"(r[0]), "=r"(r[1]), "=r"(r[2]), "=r"(r[3]) : "r"(addr));
}
__device__ __forceinline__ void mma16816(float* d, const uint32_t* a, const uint32_t* b) {
    asm volatile("mma.sync.aligned.m16n8k16.row.col.f32.bf16.bf16.f32 "
                 "{%0,%1,%2,%3}, {%4,%5,%6,%7}, {%8,%9}, {%0,%1,%2,%3};"
                 : "+f"(d[0]), "+f"(d[1]), "+f"(d[2]), "+f"(d[3])
                 : "r"(a[0]), "r"(a[1]), "r"(a[2]), "r"(a[3]), "r"(b[0]), "r"(b[1]));
}
__device__ __forceinline__ void cp16(uint32_t dst, const void* src) {
    asm volatile("cp.async.ca.shared.global [%0], [%1], 16;" :: "r"(dst), "l"(src));
}
__device__ __forceinline__ void cp_commit() {
    asm volatile("cp.async.commit_group;" ::: "memory");
}
template <int N> __device__ __forceinline__ void cp_wait() {
    asm volatile("cp.async.wait_group %0;" :: "n"(N) : "memory");
}

// ================= graph preprocessing =================

__global__ void init_kernel() {
    int i = blockIdx.x * blockDim.x + threadIdx.x;
    if (i < Nn) { g_deg[i] = 0.f; g_cur[i] = 0; }
    if (i < Hh) g_pool[i] = 0.f;
}

__global__ void deg_kernel(const int* __restrict__ ei) {
    int i = blockIdx.x * blockDim.x + threadIdx.x;
    if (i < Ee) atomicAdd(&g_deg[ei[Ee + i]], 1.0f);
}

// warp-shuffle based scan (+ fused dinv), 1024 threads
__global__ void scan_kernel() {
    __shared__ int wsum[32];
    __shared__ int carry;
    int t = threadIdx.x, lane = t & 31, w = t >> 5;
    if (t == 0) { carry = 0; g_off[0] = 0; }
    __syncthreads();
    for (int base = 0; base < Nn; base += 1024) {
        int i = base + t;
        int v = 0;
        if (i < Nn) {
            v = (int)g_deg[i] + 1;
            g_dinv[i] = rsqrtf((float)v);
        }
        int s = v;
#pragma unroll
        for (int o = 1; o < 32; o <<= 1) {
            int u = __shfl_up_sync(0xffffffffu, s, o);
            if (lane >= o) s += u;
        }
        if (lane == 31) wsum[w] = s;
        __syncthreads();
        if (w == 0) {
            int ws = wsum[lane];
#pragma unroll
            for (int o = 1; o < 32; o <<= 1) {
                int u = __shfl_up_sync(0xffffffffu, ws, o);
                if (lane >= o) ws += u;
            }
            wsum[lane] = ws;
        }
        __syncthreads();
        int boff = (w ? wsum[w - 1] : 0);
        if (i < Nn) g_off[i + 1] = carry + boff + s;
        __syncthreads();
        if (t == 0) carry += wsum[31];
        __syncthreads();
    }
}

__global__ void fill_kernel(const int* __restrict__ ei) {
    int i = blockIdx.x * blockDim.x + threadIdx.x;
    if (i >= TOT) return;
    int s, d;
    if (i < Ee) { s = ei[i]; d = ei[Ee + i]; }
    else        { s = i - Ee; d = s; }
    int pos = atomicAdd(&g_cur[d], 1);
    int idx = g_off[d] + pos;
    g_srcv[idx] = s;
    g_wv[idx]   = g_dinv[s] * g_dinv[d];
}

// ==== fused: weight transpose + hi/lo split AND layer-1 input conversion ====

#define CVT_ITEMS (Nn * DIN / 2)

__global__ void wt_cvt_kernel(const float* __restrict__ W1, const float* __restrict__ W2,
                              const float* __restrict__ W3, const float* __restrict__ W4,
                              const float* __restrict__ x) {
    int idx = blockIdx.x * blockDim.x + threadIdx.x;
    if (idx < WTOT) {
        const float* W; int K, loc;
        if (idx < WOFF2)      { W = W1; K = DIN; loc = idx; }
        else if (idx < WOFF3) { W = W2; K = Hh;  loc = idx - WOFF2; }
        else if (idx < WOFF4) { W = W3; K = Hh;  loc = idx - WOFF3; }
        else                  { W = W4; K = Hh;  loc = idx - WOFF4; }
        int n = loc / K, k = loc % K;          // output index [n][k]
        float a = W[(size_t)k * Hh + n];       // source [k][n]
        __nv_bfloat16 h = __float2bfloat16(a);
        g_wt_hi[idx] = h;
        g_wt_lo[idx] = __float2bfloat16(a - __bfloat162float(h));
    } else {
        int i = idx - WTOT;
        if (i >= CVT_ITEMS) return;
        float2 v = *(const float2*)&x[i * 2];
        __nv_bfloat162 hv = __floats2bfloat162_rn(v.x, v.y);
        *(__nv_bfloat162*)&g_a[i * 2] = hv;
    }
}

// ======= warp-MMA bf16 GEMM (weights hi/lo compensated), 2-stage cp.async ====
// C[N,512] = A[N,K] @ (WH+WL)[K,512]; A bf16, W^T pre-split hi/lo.
// CTA: 128x128 tile, 256 threads, 8 warps (4m x 2n), warp tile 32x64, BK=32.
// Rows 64 B, XOR swizzle (16B chunk c ^= (r>>1)&3). Output g_h bf16.

#define BM 128
#define BN 128
#define ARR_B 8192               // bytes per array per stage (128 rows x 64 B)
#define STG_B (3 * ARR_B)        // 24576 per stage (A, BH, BL)
#define GEMM_SMEM (2 * STG_B)    // 49152

__global__ void __launch_bounds__(256, 2)
mma_gemm(int K, int woff) {
    extern __shared__ __align__(16) char dynsmem[];
    const uint32_t sb = smem_u32(dynsmem);

    const int t    = threadIdx.x;
    const int lane = t & 31;
    const int wid  = t >> 5;
    const int wm   = (wid & 3) * 32;
    const int wn   = (wid >> 2) * 64;
    const int m0   = blockIdx.y * BM;
    const int n0   = blockIdx.x * BN;

    const __nv_bfloat16* srcp[3] = {
        g_a + (size_t)m0 * K,
        g_wt_hi + woff + (size_t)n0 * K,
        g_wt_lo + woff + (size_t)n0 * K
    };

    float acc[2][8][4];
#pragma unroll
    for (int i = 0; i < 2; i++)
#pragma unroll
        for (int j = 0; j < 8; j++)
#pragma unroll
            for (int k = 0; k < 4; k++) acc[i][j][k] = 0.f;

    const int nch = K >> 5;

    // cp.async issue of chunk c into stage c%2: 1536 16B segs, 6 per thread
    auto issue = [&](int c) {
        const uint32_t stb = sb + (uint32_t)(c & 1) * STG_B;
        const int k0 = c << 5;
#pragma unroll
        for (int i = 0; i < 6; i++) {
            int seg = t + i * 256;
            int arr = seg >> 9;
            int rem = seg & 511;
            int r   = rem >> 2;
            int sgi = rem & 3;
            uint32_t dst = stb + (uint32_t)(arr * ARR_B + r * 64 +
                                            ((sgi ^ ((r >> 1) & 3)) << 4));
            cp16(dst, srcp[arr] + (size_t)r * K + k0 + sgi * 8);
        }
        cp_commit();
    };

    // ldmatrix lane mapping
    const int arow = lane & 15, acolg = lane >> 4;
    const int brow = (lane & 7) + ((lane >> 4) << 3);
    const int bcolg = (lane >> 3) & 1;

    issue(0);

    for (int c = 0; c < nch; c++) {
        if (c + 1 < nch) { issue(c + 1); cp_wait<1>(); }
        else             { cp_wait<0>(); }
        __syncthreads();

        const uint32_t stb = sb + (uint32_t)(c & 1) * STG_B;
        const uint32_t aS = stb;
        const uint32_t bH = stb + ARR_B;
        const uint32_t bL = stb + 2 * ARR_B;

#pragma unroll
        for (int ks = 0; ks < 2; ks++) {
            uint32_t ar[2][4];
#pragma unroll
            for (int mt = 0; mt < 2; mt++) {
                int rr = wm + mt * 16 + arow;
                uint32_t off = (uint32_t)(rr * 64 +
                               (((2 * ks + acolg) ^ ((rr >> 1) & 3)) << 4));
                ldsm_x4(ar[mt], aS + off);
            }
#pragma unroll
            for (int np = 0; np < 4; np++) {
                int rr = wn + np * 16 + brow;
                uint32_t boff = (uint32_t)(rr * 64 +
                                (((2 * ks + bcolg) ^ ((rr >> 1) & 3)) << 4));
                uint32_t bh[4], bl[4];
                ldsm_x4(bh, bH + boff);
                ldsm_x4(bl, bL + boff);
#pragma unroll
                for (int mt = 0; mt < 2; mt++) {
                    mma16816(acc[mt][np * 2 + 0], ar[mt], bh + 0);
                    mma16816(acc[mt][np * 2 + 1], ar[mt], bh + 2);
                    mma16816(acc[mt][np * 2 + 0], ar[mt], bl + 0);
                    mma16816(acc[mt][np * 2 + 1], ar[mt], bl + 2);
                }
            }
        }
        __syncthreads();   // stage reuse guard
    }

    // ---- epilogue: acc -> g_h (bf16) ----
    const int quad = lane >> 2;
    const int qi   = lane & 3;
#pragma unroll
    for (int mt = 0; mt < 2; mt++) {
        int r0 = m0 + wm + mt * 16 + quad;
#pragma unroll
        for (int nt = 0; nt < 8; nt++) {
            int cc = n0 + wn + nt * 8 + qi * 2;
            if (r0 < Nn) {
                __nv_bfloat162 v = __floats2bfloat162_rn(acc[mt][nt][0], acc[mt][nt][1]);
                *(__nv_bfloat162*)&g_h[(size_t)r0 * Hh + cc] = v;
            }
            if (r0 + 8 < Nn) {
                __nv_bfloat162 v = __floats2bfloat162_rn(acc[mt][nt][2], acc[mt][nt][3]);
                *(__nv_bfloat162*)&g_h[(size_t)(r0 + 8) * Hh + cc] = v;
            }
        }
    }
}

// ======= fused CSR gather-aggregate + bias + LayerNorm + ReLU =======
// reads bf16 messages; writes bf16 activations

__global__ void __launch_bounds__(128)
agg_kernel(const float* __restrict__ bias,
           const float* __restrict__ gamma,
           const float* __restrict__ beta) {
    const int n = blockIdx.x;
    const int t = threadIdx.x;
    const int beg = g_off[n], end = g_off[n + 1];
    const int fo = t * 4;

    float4 acc = make_float4(0.f, 0.f, 0.f, 0.f);
#pragma unroll 2
    for (int j = beg; j < end; j++) {
        int   s = g_srcv[j];
        float wv = g_wv[j];
        uint2 rv = *(const uint2*)&g_h[(size_t)s * Hh + fo];
        float2 f0 = __bfloat1622float2(*(__nv_bfloat162*)&rv.x);
        float2 f1 = __bfloat1622float2(*(__nv_bfloat162*)&rv.y);
        acc.x = fmaf(wv, f0.x, acc.x);
        acc.y = fmaf(wv, f0.y, acc.y);
        acc.z = fmaf(wv, f1.x, acc.z);
        acc.w = fmaf(wv, f1.y, acc.w);
    }
    float4 b = *(const float4*)&bias[fo];
    acc.x += b.x; acc.y += b.y; acc.z += b.z; acc.w += b.w;

    float s1 = acc.x + acc.y + acc.z + acc.w;
    float s2 = acc.x * acc.x + acc.y * acc.y + acc.z * acc.z + acc.w * acc.w;
#pragma unroll
    for (int o = 16; o > 0; o >>= 1) {
        s1 += __shfl_xor_sync(0xffffffffu, s1, o);
        s2 += __shfl_xor_sync(0xffffffffu, s2, o);
    }
    __shared__ float sm1[4], sm2[4];
    if ((t & 31) == 0) { sm1[t >> 5] = s1; sm2[t >> 5] = s2; }
    __syncthreads();
    float S1 = sm1[0] + sm1[1] + sm1[2] + sm1[3];
    float S2 = sm2[0] + sm2[1] + sm2[2] + sm2[3];
    float mu  = S1 * (1.0f / Hh);
    float var = S2 * (1.0f / Hh) - mu * mu;
    float inv = rsqrtf(var + EPSL);

    float4 gm = *(const float4*)&gamma[fo];
    float4 bt = *(const float4*)&beta[fo];
    float2 y0, y1;
    y0.x = fmaxf((acc.x - mu) * inv * gm.x + bt.x, 0.f);
    y0.y = fmaxf((acc.y - mu) * inv * gm.y + bt.y, 0.f);
    y1.x = fmaxf((acc.z - mu) * inv * gm.z + bt.z, 0.f);
    y1.y = fmaxf((acc.w - mu) * inv * gm.w + bt.w, 0.f);

    uint2 hv;
    __nv_bfloat162 h0 = __floats2bfloat162_rn(y0.x, y0.y);
    __nv_bfloat162 h1 = __floats2bfloat162_rn(y1.x, y1.y);
    hv.x = *(unsigned*)&h0;
    hv.y = *(unsigned*)&h1;
    *(uint2*)&g_a[(size_t)n * Hh + fo] = hv;
}

// ================= mean pool + output projection =================

__global__ void pool_kernel() {
    int f = threadIdx.x;
    float s = 0.f;
    for (int n = blockIdx.x; n < Nn; n += gridDim.x)
        s += __bfloat162float(g_a[(size_t)n * Hh + f]);
    atomicAdd(&g_pool[f], s);
}

__global__ void out_kernel(const float* __restrict__ Wout,
                           const float* __restrict__ bout,
                           float* __restrict__ out) {
    __shared__ float sm[NOUT][256];
    int t = threadIdx.x;
    float acc[NOUT];
#pragma unroll
    for (int o = 0; o < NOUT; o++) acc[o] = 0.f;
    for (int f = t; f < Hh; f += 256) {
        float p = g_pool[f] * (1.0f / Nn);
#pragma unroll
        for (int o = 0; o < NOUT; o++)
            acc[o] = fmaf(p, Wout[f * NOUT + o], acc[o]);
    }
#pragma unroll
    for (int o = 0; o < NOUT; o++) sm[o][t] = acc[o];
    __syncthreads();
    for (int st = 128; st > 0; st >>= 1) {
        if (t < st) {
#pragma unroll
            for (int o = 0; o < NOUT; o++) sm[o][t] += sm[o][t + st];
        }
        __syncthreads();
    }
    if (t < NOUT) out[t] = sm[t][0] + bout[t];
}

// ================= launch =================

extern "C" void kernel_launch(void* const* d_in, const int* in_sizes, int n_in,
                              void* d_out, int out_size) {
    const float* x  = (const float*)d_in[0];
    const int*   ei = (const int*)d_in[1];
    const float* W1 = (const float*)d_in[2];  const float* b1 = (const float*)d_in[3];
    const float* W2 = (const float*)d_in[4];  const float* b2 = (const float*)d_in[5];
    const float* W3 = (const float*)d_in[6];  const float* b3 = (const float*)d_in[7];
    const float* W4 = (const float*)d_in[8];  const float* b4 = (const float*)d_in[9];
    const float* gm = (const float*)d_in[10]; const float* bt = (const float*)d_in[11];
    const float* Wo = (const float*)d_in[12]; const float* bo = (const float*)d_in[13];
    float* out = (float*)d_out;

    cudaFuncSetAttribute(mma_gemm, cudaFuncAttributeMaxDynamicSharedMemorySize, GEMM_SMEM);

    init_kernel<<<(Nn + 255) / 256, 256>>>();                                   // 0
    deg_kernel<<<(Ee + 255) / 256, 256>>>(ei);                                  // 1
    scan_kernel<<<1, 1024>>>();                                                 // 2
    fill_kernel<<<(TOT + 255) / 256, 256>>>(ei);                                // 3
    wt_cvt_kernel<<<(WTOT + CVT_ITEMS + 255) / 256, 256>>>(W1, W2, W3, W4, x);  // 4

    dim3 ggrid(Hh / BN, NP / BM);   // (4, 157)

    mma_gemm<<<ggrid, 256, GEMM_SMEM>>>(DIN, WOFF1);                            // 5
    agg_kernel<<<Nn, 128>>>(b1, gm, bt);
    mma_gemm<<<ggrid, 256, GEMM_SMEM>>>(Hh, WOFF2);
    agg_kernel<<<Nn, 128>>>(b2, gm, bt);
    mma_gemm<<<ggrid, 256, GEMM_SMEM>>>(Hh, WOFF3);
    agg_kernel<<<Nn, 128>>>(b3, gm, bt);
    mma_gemm<<<ggrid, 256, GEMM_SMEM>>>(Hh, WOFF4);
    agg_kernel<<<Nn, 128>>>(b4, gm, bt);

    pool_kernel<<<148, 512>>>();
    out_kernel<<<1, 256>>>(Wo, bo, out);
}

// round 12
// speedup vs baseline: 1.3018x; 1.0302x over previous
#include <cuda_runtime.h>
#include <cuda_bf16.h>
#include <cstdint>

#define Nn   20000
#define NP   20096            // padded rows (157 * 128)
#define Ee   320000
#define DIN  128
#define Hh   512
#define NOUT 7
#define TOT  (Ee + Nn)
#define EPSL 1e-5f

// Wt layout: layer1 [512][128] then layers 2-4 [512][512] (hi and lo arrays)
#define WOFF1 0
#define WOFF2 65536
#define WOFF3 327680
#define WOFF4 589824
#define WTOT  851968

// ---- scratch (no allocs allowed: __device__ globals) ----
__device__ __nv_bfloat16 g_h[(size_t)Nn * Hh];          // GEMM output (bf16)
__device__ __nv_bfloat16 g_a[(size_t)NP * Hh];          // activations (bf16, padded)
__device__ float g_deg[Nn];
__device__ float g_dinv[Nn];
__device__ int   g_off[Nn + 1];
__device__ int   g_cur[Nn];
__device__ int   g_srcv[TOT];
__device__ float g_wv[TOT];
__device__ float g_pool[Hh];
__device__ __nv_bfloat16 g_wt_hi[WTOT];
__device__ __nv_bfloat16 g_wt_lo[WTOT];

// ================= helpers =================

__device__ __forceinline__ uint32_t smem_u32(const void* p) {
    uint32_t a;
    asm("{ .reg .u64 t; cvta.to.shared.u64 t, %1; cvt.u32.u64 %0, t; }" : "=r"(a) : "l"(p));
    return a;
}
__device__ __forceinline__ void ldsm_x4(uint32_t* r, uint32_t addr) {
    asm volatile("ldmatrix.sync.aligned.m8n8.x4.shared.b16 {%0,%1,%2,%3}, [%4];"
                 : "=r"(r[0]), "=r"(r[1]), "=r"(r[2]), "=r"(r[3]) : "r"(addr));
}
__device__ __forceinline__ void mma16816(float* d, const uint32_t* a, const uint32_t* b) {
    asm volatile("mma.sync.aligned.m16n8k16.row.col.f32.bf16.bf16.f32 "
                 "{%0,%1,%2,%3}, {%4,%5,%6,%7}, {%8,%9}, {%0,%1,%2,%3};"
                 : "+f"(d[0]), "+f"(d[1]), "+f"(d[2]), "+f"(d[3])
                 : "r"(a[0]), "r"(a[1]), "r"(a[2]), "r"(a[3]), "r"(b[0]), "r"(b[1]));
}
__device__ __forceinline__ void cp16(uint32_t dst, const void* src) {
    asm volatile("cp.async.ca.shared.global [%0], [%1], 16;" :: "r"(dst), "l"(src));
}
__device__ __forceinline__ void cp_commit() {
    asm volatile("cp.async.commit_group;" ::: "memory");
}
template <int N> __device__ __forceinline__ void cp_wait() {
    asm volatile("cp.async.wait_group %0;" :: "n"(N) : "memory");
}

// ================= graph preprocessing =================

__global__ void deg_kernel(const int* __restrict__ ei) {
    int i = blockIdx.x * blockDim.x + threadIdx.x;
    if (i < Ee) atomicAdd(&g_deg[ei[Ee + i]], 1.0f);
}

// warp-shuffle based scan (+ fused dinv), 1024 threads
__global__ void scan_kernel() {
    __shared__ int wsum[32];
    __shared__ int carry;
    int t = threadIdx.x, lane = t & 31, w = t >> 5;
    if (t == 0) { carry = 0; g_off[0] = 0; }
    __syncthreads();
    for (int base = 0; base < Nn; base += 1024) {
        int i = base + t;
        int v = 0;
        if (i < Nn) {
            v = (int)g_deg[i] + 1;
            g_dinv[i] = rsqrtf((float)v);
        }
        int s = v;
#pragma unroll
        for (int o = 1; o < 32; o <<= 1) {
            int u = __shfl_up_sync(0xffffffffu, s, o);
            if (lane >= o) s += u;
        }
        if (lane == 31) wsum[w] = s;
        __syncthreads();
        if (w == 0) {
            int ws = wsum[lane];
#pragma unroll
            for (int o = 1; o < 32; o <<= 1) {
                int u = __shfl_up_sync(0xffffffffu, ws, o);
                if (lane >= o) ws += u;
            }
            wsum[lane] = ws;
        }
        __syncthreads();
        int boff = (w ? wsum[w - 1] : 0);
        if (i < Nn) g_off[i + 1] = carry + boff + s;
        __syncthreads();
        if (t == 0) carry += wsum[31];
        __syncthreads();
    }
}

__global__ void fill_kernel(const int* __restrict__ ei) {
    int i = blockIdx.x * blockDim.x + threadIdx.x;
    if (i >= TOT) return;
    int s, d;
    if (i < Ee) { s = ei[i]; d = ei[Ee + i]; }
    else        { s = i - Ee; d = s; }
    int pos = atomicAdd(&g_cur[d], 1);
    int idx = g_off[d] + pos;
    g_srcv[idx] = s;
    g_wv[idx]   = g_dinv[s] * g_dinv[d];
}

// == fused: weight transpose/split + layer-1 input cvt + scratch zeroing ==

#define CVT_ITEMS (Nn * DIN / 2)
#define PREP_TOT  (WTOT + CVT_ITEMS + Nn)

__global__ void wt_cvt_kernel(const float* __restrict__ W1, const float* __restrict__ W2,
                              const float* __restrict__ W3, const float* __restrict__ W4,
                              const float* __restrict__ x) {
    int idx = blockIdx.x * blockDim.x + threadIdx.x;
    if (idx < WTOT) {
        const float* W; int K, loc;
        if (idx < WOFF2)      { W = W1; K = DIN; loc = idx; }
        else if (idx < WOFF3) { W = W2; K = Hh;  loc = idx - WOFF2; }
        else if (idx < WOFF4) { W = W3; K = Hh;  loc = idx - WOFF3; }
        else                  { W = W4; K = Hh;  loc = idx - WOFF4; }
        int n = loc / K, k = loc % K;          // output index [n][k]
        float a = W[(size_t)k * Hh + n];       // source [k][n]
        __nv_bfloat16 h = __float2bfloat16(a);
        g_wt_hi[idx] = h;
        g_wt_lo[idx] = __float2bfloat16(a - __bfloat162float(h));
    } else if (idx < WTOT + CVT_ITEMS) {
        int i = idx - WTOT;
        float2 v = *(const float2*)&x[i * 2];
        __nv_bfloat162 hv = __floats2bfloat162_rn(v.x, v.y);
        *(__nv_bfloat162*)&g_a[i * 2] = hv;
    } else {
        int i = idx - WTOT - CVT_ITEMS;   // 0..Nn-1: zero scratch
        g_deg[i] = 0.f;
        g_cur[i] = 0;
        if (i < Hh) g_pool[i] = 0.f;
    }
}

// ======= warp-MMA bf16 GEMM (weights hi/lo compensated), 2-stage cp.async ====
// C[N,512] = A[N,K] @ (WH+WL)[K,512]; A bf16, W^T pre-split hi/lo.
// CTA: 128x128 tile, 256 threads, 8 warps (4m x 2n), warp tile 32x64, BK=32.
// Rows 64 B, XOR swizzle (16B chunk c ^= (r>>1)&3). Output g_h bf16.

#define BM 128
#define BN 128
#define ARR_B 8192               // bytes per array per stage (128 rows x 64 B)
#define STG_B (3 * ARR_B)        // 24576 per stage (A, BH, BL)
#define GEMM_SMEM (2 * STG_B)    // 49152

__global__ void __launch_bounds__(256, 2)
mma_gemm(int K, int woff) {
    extern __shared__ __align__(16) char dynsmem[];
    const uint32_t sb = smem_u32(dynsmem);

    const int t    = threadIdx.x;
    const int lane = t & 31;
    const int wid  = t >> 5;
    const int wm   = (wid & 3) * 32;
    const int wn   = (wid >> 2) * 64;
    const int m0   = blockIdx.y * BM;
    const int n0   = blockIdx.x * BN;

    const __nv_bfloat16* srcp[3] = {
        g_a + (size_t)m0 * K,
        g_wt_hi + woff + (size_t)n0 * K,
        g_wt_lo + woff + (size_t)n0 * K
    };

    float acc[2][8][4];
#pragma unroll
    for (int i = 0; i < 2; i++)
#pragma unroll
        for (int j = 0; j < 8; j++)
#pragma unroll
            for (int k = 0; k < 4; k++) acc[i][j][k] = 0.f;

    const int nch = K >> 5;

    // cp.async issue of chunk c into stage c%2: 1536 16B segs, 6 per thread
    auto issue = [&](int c) {
        const uint32_t stb = sb + (uint32_t)(c & 1) * STG_B;
        const int k0 = c << 5;
#pragma unroll
        for (int i = 0; i < 6; i++) {
            int seg = t + i * 256;
            int arr = seg >> 9;
            int rem = seg & 511;
            int r   = rem >> 2;
            int sgi = rem & 3;
            uint32_t dst = stb + (uint32_t)(arr * ARR_B + r * 64 +
                                            ((sgi ^ ((r >> 1) & 3)) << 4));
            cp16(dst, srcp[arr] + (size_t)r * K + k0 + sgi * 8);
        }
        cp_commit();
    };

    // ldmatrix lane mapping
    const int arow = lane & 15, acolg = lane >> 4;
    const int brow = (lane & 7) + ((lane >> 4) << 3);
    const int bcolg = (lane >> 3) & 1;

    issue(0);

    for (int c = 0; c < nch; c++) {
        if (c + 1 < nch) { issue(c + 1); cp_wait<1>(); }
        else             { cp_wait<0>(); }
        __syncthreads();

        const uint32_t stb = sb + (uint32_t)(c & 1) * STG_B;
        const uint32_t aS = stb;
        const uint32_t bH = stb + ARR_B;
        const uint32_t bL = stb + 2 * ARR_B;

#pragma unroll
        for (int ks = 0; ks < 2; ks++) {
            uint32_t ar[2][4];
#pragma unroll
            for (int mt = 0; mt < 2; mt++) {
                int rr = wm + mt * 16 + arow;
                uint32_t off = (uint32_t)(rr * 64 +
                               (((2 * ks + acolg) ^ ((rr >> 1) & 3)) << 4));
                ldsm_x4(ar[mt], aS + off);
            }
#pragma unroll
            for (int np = 0; np < 4; np++) {
                int rr = wn + np * 16 + brow;
                uint32_t boff = (uint32_t)(rr * 64 +
                                (((2 * ks + bcolg) ^ ((rr >> 1) & 3)) << 4));
                uint32_t bh[4], bl[4];
                ldsm_x4(bh, bH + boff);
                ldsm_x4(bl, bL + boff);
#pragma unroll
                for (int mt = 0; mt < 2; mt++) {
                    mma16816(acc[mt][np * 2 + 0], ar[mt], bh + 0);
                    mma16816(acc[mt][np * 2 + 1], ar[mt], bh + 2);
                    mma16816(acc[mt][np * 2 + 0], ar[mt], bl + 0);
                    mma16816(acc[mt][np * 2 + 1], ar[mt], bl + 2);
                }
            }
        }
        __syncthreads();   // stage reuse guard
    }

    // ---- epilogue: acc -> g_h (bf16) ----
    const int quad = lane >> 2;
    const int qi   = lane & 3;
#pragma unroll
    for (int mt = 0; mt < 2; mt++) {
        int r0 = m0 + wm + mt * 16 + quad;
#pragma unroll
        for (int nt = 0; nt < 8; nt++) {
            int cc = n0 + wn + nt * 8 + qi * 2;
            if (r0 < Nn) {
                __nv_bfloat162 v = __floats2bfloat162_rn(acc[mt][nt][0], acc[mt][nt][1]);
                *(__nv_bfloat162*)&g_h[(size_t)r0 * Hh + cc] = v;
            }
            if (r0 + 8 < Nn) {
                __nv_bfloat162 v = __floats2bfloat162_rn(acc[mt][nt][2], acc[mt][nt][3]);
                *(__nv_bfloat162*)&g_h[(size_t)(r0 + 8) * Hh + cc] = v;
            }
        }
    }
}

// ======= fused CSR gather-aggregate + bias + LayerNorm + ReLU =======
// 2 nodes per 256-thread block; 128 threads per node; unroll-4 gather (MLP=4).

__global__ void __launch_bounds__(256)
agg_kernel(const float* __restrict__ bias,
           const float* __restrict__ gamma,
           const float* __restrict__ beta) {
    const int grp = threadIdx.x >> 7;            // 0 or 1
    const int n   = blockIdx.x * 2 + grp;
    const int t   = threadIdx.x & 127;
    const int beg = g_off[n], end = g_off[n + 1];
    const int fo  = t * 4;

    float4 acc = make_float4(0.f, 0.f, 0.f, 0.f);
    int j = beg;
    for (; j + 3 < end; j += 4) {
        int   s0 = g_srcv[j],     s1 = g_srcv[j + 1];
        int   s2 = g_srcv[j + 2], s3 = g_srcv[j + 3];
        float w0 = g_wv[j],       w1 = g_wv[j + 1];
        float w2 = g_wv[j + 2],   w3 = g_wv[j + 3];
        uint2 r0 = *(const uint2*)&g_h[(size_t)s0 * Hh + fo];
        uint2 r1 = *(const uint2*)&g_h[(size_t)s1 * Hh + fo];
        uint2 r2 = *(const uint2*)&g_h[(size_t)s2 * Hh + fo];
        uint2 r3 = *(const uint2*)&g_h[(size_t)s3 * Hh + fo];
        float2 a0 = __bfloat1622float2(*(__nv_bfloat162*)&r0.x);
        float2 b0 = __bfloat1622float2(*(__nv_bfloat162*)&r0.y);
        float2 a1 = __bfloat1622float2(*(__nv_bfloat162*)&r1.x);
        float2 b1 = __bfloat1622float2(*(__nv_bfloat162*)&r1.y);
        float2 a2 = __bfloat1622float2(*(__nv_bfloat162*)&r2.x);
        float2 b2 = __bfloat1622float2(*(__nv_bfloat162*)&r2.y);
        float2 a3 = __bfloat1622float2(*(__nv_bfloat162*)&r3.x);
        float2 b3 = __bfloat1622float2(*(__nv_bfloat162*)&r3.y);
        acc.x = fmaf(w0, a0.x, fmaf(w1, a1.x, fmaf(w2, a2.x, fmaf(w3, a3.x, acc.x))));
        acc.y = fmaf(w0, a0.y, fmaf(w1, a1.y, fmaf(w2, a2.y, fmaf(w3, a3.y, acc.y))));
        acc.z = fmaf(w0, b0.x, fmaf(w1, b1.x, fmaf(w2, b2.x, fmaf(w3, b3.x, acc.z))));
        acc.w = fmaf(w0, b0.y, fmaf(w1, b1.y, fmaf(w2, b2.y, fmaf(w3, b3.y, acc.w))));
    }
    for (; j < end; j++) {
        int   s = g_srcv[j];
        float wv = g_wv[j];
        uint2 rv = *(const uint2*)&g_h[(size_t)s * Hh + fo];
        float2 f0 = __bfloat1622float2(*(__nv_bfloat162*)&rv.x);
        float2 f1 = __bfloat1622float2(*(__nv_bfloat162*)&rv.y);
        acc.x = fmaf(wv, f0.x, acc.x);
        acc.y = fmaf(wv, f0.y, acc.y);
        acc.z = fmaf(wv, f1.x, acc.z);
        acc.w = fmaf(wv, f1.y, acc.w);
    }
    float4 b = *(const float4*)&bias[fo];
    acc.x += b.x; acc.y += b.y; acc.z += b.z; acc.w += b.w;

    float s1 = acc.x + acc.y + acc.z + acc.w;
    float s2 = acc.x * acc.x + acc.y * acc.y + acc.z * acc.z + acc.w * acc.w;
#pragma unroll
    for (int o = 16; o > 0; o >>= 1) {
        s1 += __shfl_xor_sync(0xffffffffu, s1, o);
        s2 += __shfl_xor_sync(0xffffffffu, s2, o);
    }
    __shared__ float sm1[8], sm2[8];
    const int wslot = grp * 4 + ((t >> 5) & 3);
    if ((t & 31) == 0) { sm1[wslot] = s1; sm2[wslot] = s2; }
    __syncthreads();
    float S1 = sm1[grp * 4] + sm1[grp * 4 + 1] + sm1[grp * 4 + 2] + sm1[grp * 4 + 3];
    float S2 = sm2[grp * 4] + sm2[grp * 4 + 1] + sm2[grp * 4 + 2] + sm2[grp * 4 + 3];
    float mu  = S1 * (1.0f / Hh);
    float var = S2 * (1.0f / Hh) - mu * mu;
    float inv = rsqrtf(var + EPSL);

    float4 gm = *(const float4*)&gamma[fo];
    float4 bt = *(const float4*)&beta[fo];
    float2 y0, y1;
    y0.x = fmaxf((acc.x - mu) * inv * gm.x + bt.x, 0.f);
    y0.y = fmaxf((acc.y - mu) * inv * gm.y + bt.y, 0.f);
    y1.x = fmaxf((acc.z - mu) * inv * gm.z + bt.z, 0.f);
    y1.y = fmaxf((acc.w - mu) * inv * gm.w + bt.w, 0.f);

    uint2 hv;
    __nv_bfloat162 h0 = __floats2bfloat162_rn(y0.x, y0.y);
    __nv_bfloat162 h1 = __floats2bfloat162_rn(y1.x, y1.y);
    hv.x = *(unsigned*)&h0;
    hv.y = *(unsigned*)&h1;
    *(uint2*)&g_a[(size_t)n * Hh + fo] = hv;
}

// ================= mean pool + output projection =================

__global__ void pool_kernel() {
    int f = threadIdx.x;
    float s = 0.f;
    for (int n = blockIdx.x; n < Nn; n += gridDim.x)
        s += __bfloat162float(g_a[(size_t)n * Hh + f]);
    atomicAdd(&g_pool[f], s);
}

__global__ void out_kernel(const float* __restrict__ Wout,
                           const float* __restrict__ bout,
                           float* __restrict__ out) {
    __shared__ float sm[NOUT][256];
    int t = threadIdx.x;
    float acc[NOUT];
#pragma unroll
    for (int o = 0; o < NOUT; o++) acc[o] = 0.f;
    for (int f = t; f < Hh; f += 256) {
        float p = g_pool[f] * (1.0f / Nn);
#pragma unroll
        for (int o = 0; o < NOUT; o++)
            acc[o] = fmaf(p, Wout[f * NOUT + o], acc[o]);
    }
#pragma unroll
    for (int o = 0; o < NOUT; o++) sm[o][t] = acc[o];
    __syncthreads();
    for (int st = 128; st > 0; st >>= 1) {
        if (t < st) {
#pragma unroll
            for (int o = 0; o < NOUT; o++) sm[o][t] += sm[o][t + st];
        }
        __syncthreads();
    }
    if (t < NOUT) out[t] = sm[t][0] + bout[t];
}

// ================= launch =================

extern "C" void kernel_launch(void* const* d_in, const int* in_sizes, int n_in,
                              void* d_out, int out_size) {
    const float* x  = (const float*)d_in[0];
    const int*   ei = (const int*)d_in[1];
    const float* W1 = (const float*)d_in[2];  const float* b1 = (const float*)d_in[3];
    const float* W2 = (const float*)d_in[4];  const float* b2 = (const float*)d_in[5];
    const float* W3 = (const float*)d_in[6];  const float* b3 = (const float*)d_in[7];
    const float* W4 = (const float*)d_in[8];  const float* b4 = (const float*)d_in[9];
    const float* gm = (const float*)d_in[10]; const float* bt = (const float*)d_in[11];
    const float* Wo = (const float*)d_in[12]; const float* bo = (const float*)d_in[13];
    float* out = (float*)d_out;

    cudaFuncSetAttribute(mma_gemm, cudaFuncAttributeMaxDynamicSharedMemorySize, GEMM_SMEM);

    wt_cvt_kernel<<<(PREP_TOT + 255) / 256, 256>>>(W1, W2, W3, W4, x);   // 0 (zeroes scratch)
    deg_kernel<<<(Ee + 255) / 256, 256>>>(ei);                           // 1
    scan_kernel<<<1, 1024>>>();                                          // 2
    fill_kernel<<<(TOT + 255) / 256, 256>>>(ei);                         // 3

    dim3 ggrid(Hh / BN, NP / BM);   // (4, 157)

    mma_gemm<<<ggrid, 256, GEMM_SMEM>>>(DIN, WOFF1);                     // 4
    agg_kernel<<<Nn / 2, 256>>>(b1, gm, bt);                             // 5 (profiled)
    mma_gemm<<<ggrid, 256, GEMM_SMEM>>>(Hh, WOFF2);
    agg_kernel<<<Nn / 2, 256>>>(b2, gm, bt);
    mma_gemm<<<ggrid, 256, GEMM_SMEM>>>(Hh, WOFF3);
    agg_kernel<<<Nn / 2, 256>>>(b3, gm, bt);
    mma_gemm<<<ggrid, 256, GEMM_SMEM>>>(Hh, WOFF4);
    agg_kernel<<<Nn / 2, 256>>>(b4, gm, bt);

    pool_kernel<<<148, 512>>>();
    out_kernel<<<1, 256>>>(Wo, bo, out);
}

// round 16
// speedup vs baseline: 1.3493x; 1.0364x over previous
#include <cuda_runtime.h>
#include <cuda_bf16.h>
#include <cstdint>

#define Nn   20000
#define NP   20096            // padded rows (157 * 128)
#define Ee   320000
#define DIN  128
#define Hh   512
#define NOUT 7
#define TOT  (Ee + Nn)
#define EPSL 1e-5f

// Wt layout: layer1 [512][128] then layers 2-4 [512][512] (hi and lo arrays)
#define WOFF1 0
#define WOFF2 65536
#define WOFF3 327680
#define WOFF4 589824
#define WTOT  851968

// ---- scratch (no allocs allowed: __device__ globals) ----
__device__ __nv_bfloat16 g_h[(size_t)Nn * Hh];          // GEMM output (bf16)
__device__ __nv_bfloat16 g_a[(size_t)NP * Hh];          // activations (bf16, padded)
__device__ __nv_bfloat16 g_ax[(size_t)NP * DIN];        // layer-1 aggregated input
__device__ float g_deg[Nn];
__device__ float g_dinv[Nn];
__device__ int   g_off[Nn + 1];
__device__ int   g_cur[Nn];
__device__ int   g_srcv[TOT];
__device__ float g_wv[TOT];
__device__ float g_pool[Hh];
__device__ __nv_bfloat16 g_wt_hi[WTOT];
__device__ __nv_bfloat16 g_wt_lo[WTOT];

// ================= helpers =================

__device__ __forceinline__ uint32_t smem_u32(const void* p) {
    uint32_t a;
    asm("{ .reg .u64 t; cvta.to.shared.u64 t, %1; cvt.u32.u64 %0, t; }" : "=r"(a) : "l"(p));
    return a;
}
__device__ __forceinline__ void ldsm_x4(uint32_t* r, uint32_t addr) {
    asm volatile("ldmatrix.sync.aligned.m8n8.x4.shared.b16 {%0,%1,%2,%3}, [%4];"
                 : "=r"(r[0]), "=r"(r[1]), "=r"(r[2]), "=r"(r[3]) : "r"(addr));
}
__device__ __forceinline__ void mma16816(float* d, const uint32_t* a, const uint32_t* b) {
    asm volatile("mma.sync.aligned.m16n8k16.row.col.f32.bf16.bf16.f32 "
                 "{%0,%1,%2,%3}, {%4,%5,%6,%7}, {%8,%9}, {%0,%1,%2,%3};"
                 : "+f"(d[0]), "+f"(d[1]), "+f"(d[2]), "+f"(d[3])
                 : "r"(a[0]), "r"(a[1]), "r"(a[2]), "r"(a[3]), "r"(b[0]), "r"(b[1]));
}
__device__ __forceinline__ void cp16(uint32_t dst, const void* src) {
    asm volatile("cp.async.ca.shared.global [%0], [%1], 16;" :: "r"(dst), "l"(src));
}
__device__ __forceinline__ void cp_commit() {
    asm volatile("cp.async.commit_group;" ::: "memory");
}
template <int N> __device__ __forceinline__ void cp_wait() {
    asm volatile("cp.async.wait_group %0;" :: "n"(N) : "memory");
}

// ================= graph preprocessing =================

__global__ void deg_kernel(const int* __restrict__ ei) {
    int i = blockIdx.x * blockDim.x + threadIdx.x;
    if (i < Ee) atomicAdd(&g_deg[ei[Ee + i]], 1.0f);
}

// warp-shuffle based scan (+ fused dinv), 1024 threads
__global__ void scan_kernel() {
    __shared__ int wsum[32];
    __shared__ int carry;
    int t = threadIdx.x, lane = t & 31, w = t >> 5;
    if (t == 0) { carry = 0; g_off[0] = 0; }
    __syncthreads();
    for (int base = 0; base < Nn; base += 1024) {
        int i = base + t;
        int v = 0;
        if (i < Nn) {
            v = (int)g_deg[i] + 1;
            g_dinv[i] = rsqrtf((float)v);
        }
        int s = v;
#pragma unroll
        for (int o = 1; o < 32; o <<= 1) {
            int u = __shfl_up_sync(0xffffffffu, s, o);
            if (lane >= o) s += u;
        }
        if (lane == 31) wsum[w] = s;
        __syncthreads();
        if (w == 0) {
            int ws = wsum[lane];
#pragma unroll
            for (int o = 1; o < 32; o <<= 1) {
                int u = __shfl_up_sync(0xffffffffu, ws, o);
                if (lane >= o) ws += u;
            }
            wsum[lane] = ws;
        }
        __syncthreads();
        int boff = (w ? wsum[w - 1] : 0);
        if (i < Nn) g_off[i + 1] = carry + boff + s;
        __syncthreads();
        if (t == 0) carry += wsum[31];
        __syncthreads();
    }
}

__global__ void fill_kernel(const int* __restrict__ ei) {
    int i = blockIdx.x * blockDim.x + threadIdx.x;
    if (i >= TOT) return;
    int s, d;
    if (i < Ee) { s = ei[i]; d = ei[Ee + i]; }
    else        { s = i - Ee; d = s; }
    int pos = atomicAdd(&g_cur[d], 1);
    int idx = g_off[d] + pos;
    g_srcv[idx] = s;
    g_wv[idx]   = g_dinv[s] * g_dinv[d];
}

// == fused: weight transpose/split + layer-1 input cvt + scratch zeroing ==

#define CVT_ITEMS (Nn * DIN / 2)
#define PREP_TOT  (WTOT + CVT_ITEMS + Nn)

__global__ void wt_cvt_kernel(const float* __restrict__ W1, const float* __restrict__ W2,
                              const float* __restrict__ W3, const float* __restrict__ W4,
                              const float* __restrict__ x) {
    int idx = blockIdx.x * blockDim.x + threadIdx.x;
    if (idx < WTOT) {
        const float* W; int K, loc;
        if (idx < WOFF2)      { W = W1; K = DIN; loc = idx; }
        else if (idx < WOFF3) { W = W2; K = Hh;  loc = idx - WOFF2; }
        else if (idx < WOFF4) { W = W3; K = Hh;  loc = idx - WOFF3; }
        else                  { W = W4; K = Hh;  loc = idx - WOFF4; }
        int n = loc / K, k = loc % K;          // output index [n][k]
        float a = W[(size_t)k * Hh + n];       // source [k][n]
        __nv_bfloat16 h = __float2bfloat16(a);
        g_wt_hi[idx] = h;
        g_wt_lo[idx] = __float2bfloat16(a - __bfloat162float(h));
    } else if (idx < WTOT + CVT_ITEMS) {
        int i = idx - WTOT;
        float2 v = *(const float2*)&x[i * 2];
        __nv_bfloat162 hv = __floats2bfloat162_rn(v.x, v.y);
        *(__nv_bfloat162*)&g_a[i * 2] = hv;    // layer-1 x as dense [Nn,128] in g_a
    } else {
        int i = idx - WTOT - CVT_ITEMS;   // 0..Nn-1: zero scratch
        g_deg[i] = 0.f;
        g_cur[i] = 0;
        if (i < Hh) g_pool[i] = 0.f;
    }
}

// ===== layer-1 aggregation on 128-dim input (aggregate-before-transform) ====
// one warp per node; lane covers 4 dims (uint2). 8 nodes / 256-thread block.

__global__ void __launch_bounds__(256)
agg1_kernel() {
    const int wrp  = threadIdx.x >> 5;
    const int lane = threadIdx.x & 31;
    const int n    = blockIdx.x * 8 + wrp;
    if (n >= Nn) return;
    const int beg = g_off[n], end = g_off[n + 1];
    const int fo  = lane * 4;

    float4 acc = make_float4(0.f, 0.f, 0.f, 0.f);
    int j = beg;
    for (; j + 1 < end; j += 2) {
        int   s0 = g_srcv[j],   s1 = g_srcv[j + 1];
        float w0 = g_wv[j],     w1 = g_wv[j + 1];
        uint2 r0 = *(const uint2*)&g_a[(size_t)s0 * DIN + fo];
        uint2 r1 = *(const uint2*)&g_a[(size_t)s1 * DIN + fo];
        float2 a0 = __bfloat1622float2(*(__nv_bfloat162*)&r0.x);
        float2 b0 = __bfloat1622float2(*(__nv_bfloat162*)&r0.y);
        float2 a1 = __bfloat1622float2(*(__nv_bfloat162*)&r1.x);
        float2 b1 = __bfloat1622float2(*(__nv_bfloat162*)&r1.y);
        acc.x = fmaf(w0, a0.x, fmaf(w1, a1.x, acc.x));
        acc.y = fmaf(w0, a0.y, fmaf(w1, a1.y, acc.y));
        acc.z = fmaf(w0, b0.x, fmaf(w1, b1.x, acc.z));
        acc.w = fmaf(w0, b0.y, fmaf(w1, b1.y, acc.w));
    }
    if (j < end) {
        int   s = g_srcv[j];
        float wv = g_wv[j];
        uint2 rv = *(const uint2*)&g_a[(size_t)s * DIN + fo];
        float2 f0 = __bfloat1622float2(*(__nv_bfloat162*)&rv.x);
        float2 f1 = __bfloat1622float2(*(__nv_bfloat162*)&rv.y);
        acc.x = fmaf(wv, f0.x, acc.x);
        acc.y = fmaf(wv, f0.y, acc.y);
        acc.z = fmaf(wv, f1.x, acc.z);
        acc.w = fmaf(wv, f1.y, acc.w);
    }
    uint2 hv;
    __nv_bfloat162 h0 = __floats2bfloat162_rn(acc.x, acc.y);
    __nv_bfloat162 h1 = __floats2bfloat162_rn(acc.z, acc.w);
    hv.x = *(unsigned*)&h0;
    hv.y = *(unsigned*)&h1;
    *(uint2*)&g_ax[(size_t)n * DIN + fo] = hv;
}

// ====== layer-1 bias + LayerNorm + ReLU (no gather): g_h -> g_a [Nn,512] ====

__global__ void __launch_bounds__(256)
ln_kernel(const float* __restrict__ bias,
          const float* __restrict__ gamma,
          const float* __restrict__ beta) {
    const int grp = threadIdx.x >> 7;
    const int n   = blockIdx.x * 2 + grp;
    const int t   = threadIdx.x & 127;
    const int fo  = t * 4;

    uint2 rv = *(const uint2*)&g_h[(size_t)n * Hh + fo];
    float2 f0 = __bfloat1622float2(*(__nv_bfloat162*)&rv.x);
    float2 f1 = __bfloat1622float2(*(__nv_bfloat162*)&rv.y);
    float4 b = *(const float4*)&bias[fo];
    float4 acc = make_float4(f0.x + b.x, f0.y + b.y, f1.x + b.z, f1.y + b.w);

    float s1 = acc.x + acc.y + acc.z + acc.w;
    float s2 = acc.x * acc.x + acc.y * acc.y + acc.z * acc.z + acc.w * acc.w;
#pragma unroll
    for (int o = 16; o > 0; o >>= 1) {
        s1 += __shfl_xor_sync(0xffffffffu, s1, o);
        s2 += __shfl_xor_sync(0xffffffffu, s2, o);
    }
    __shared__ float sm1[8], sm2[8];
    const int wslot = grp * 4 + ((t >> 5) & 3);
    if ((t & 31) == 0) { sm1[wslot] = s1; sm2[wslot] = s2; }
    __syncthreads();
    float S1 = sm1[grp * 4] + sm1[grp * 4 + 1] + sm1[grp * 4 + 2] + sm1[grp * 4 + 3];
    float S2 = sm2[grp * 4] + sm2[grp * 4 + 1] + sm2[grp * 4 + 2] + sm2[grp * 4 + 3];
    float mu  = S1 * (1.0f / Hh);
    float var = S2 * (1.0f / Hh) - mu * mu;
    float inv = rsqrtf(var + EPSL);

    float4 gm = *(const float4*)&gamma[fo];
    float4 bt = *(const float4*)&beta[fo];
    float2 y0, y1;
    y0.x = fmaxf((acc.x - mu) * inv * gm.x + bt.x, 0.f);
    y0.y = fmaxf((acc.y - mu) * inv * gm.y + bt.y, 0.f);
    y1.x = fmaxf((acc.z - mu) * inv * gm.z + bt.z, 0.f);
    y1.y = fmaxf((acc.w - mu) * inv * gm.w + bt.w, 0.f);

    uint2 hv;
    __nv_bfloat162 h0 = __floats2bfloat162_rn(y0.x, y0.y);
    __nv_bfloat162 h1 = __floats2bfloat162_rn(y1.x, y1.y);
    hv.x = *(unsigned*)&h0;
    hv.y = *(unsigned*)&h1;
    *(uint2*)&g_a[(size_t)n * Hh + fo] = hv;
}

// ======= warp-MMA bf16 GEMM (weights hi/lo compensated), 2-stage cp.async ====
// asel: 0 -> A = g_ax (K=128), 1 -> A = g_a (K=512). Resolved in device code.

#define BM 128
#define BN 128
#define ARR_B 8192               // bytes per array per stage (128 rows x 64 B)
#define STG_B (3 * ARR_B)        // 24576 per stage (A, BH, BL)
#define GEMM_SMEM (2 * STG_B)    // 49152

__global__ void __launch_bounds__(256, 2)
mma_gemm(int asel, int K, int woff) {
    extern __shared__ __align__(16) char dynsmem[];
    const uint32_t sb = smem_u32(dynsmem);

    const int t    = threadIdx.x;
    const int lane = t & 31;
    const int wid  = t >> 5;
    const int wm   = (wid & 3) * 32;
    const int wn   = (wid >> 2) * 64;
    const int m0   = blockIdx.y * BM;
    const int n0   = blockIdx.x * BN;

    const __nv_bfloat16* Abase = asel ? g_a : g_ax;   // device-side symbol resolution
    const __nv_bfloat16* srcp[3] = {
        Abase + (size_t)m0 * K,
        g_wt_hi + woff + (size_t)n0 * K,
        g_wt_lo + woff + (size_t)n0 * K
    };

    float acc[2][8][4];
#pragma unroll
    for (int i = 0; i < 2; i++)
#pragma unroll
        for (int j = 0; j < 8; j++)
#pragma unroll
            for (int k = 0; k < 4; k++) acc[i][j][k] = 0.f;

    const int nch = K >> 5;

    auto issue = [&](int c) {
        const uint32_t stb = sb + (uint32_t)(c & 1) * STG_B;
        const int k0 = c << 5;
#pragma unroll
        for (int i = 0; i < 6; i++) {
            int seg = t + i * 256;
            int arr = seg >> 9;
            int rem = seg & 511;
            int r   = rem >> 2;
            int sgi = rem & 3;
            uint32_t dst = stb + (uint32_t)(arr * ARR_B + r * 64 +
                                            ((sgi ^ ((r >> 1) & 3)) << 4));
            cp16(dst, srcp[arr] + (size_t)r * K + k0 + sgi * 8);
        }
        cp_commit();
    };

    const int arow = lane & 15, acolg = lane >> 4;
    const int brow = (lane & 7) + ((lane >> 4) << 3);
    const int bcolg = (lane >> 3) & 1;

    issue(0);

    for (int c = 0; c < nch; c++) {
        if (c + 1 < nch) { issue(c + 1); cp_wait<1>(); }
        else             { cp_wait<0>(); }
        __syncthreads();

        const uint32_t stb = sb + (uint32_t)(c & 1) * STG_B;
        const uint32_t aS = stb;
        const uint32_t bH = stb + ARR_B;
        const uint32_t bL = stb + 2 * ARR_B;

#pragma unroll
        for (int ks = 0; ks < 2; ks++) {
            uint32_t ar[2][4];
#pragma unroll
            for (int mt = 0; mt < 2; mt++) {
                int rr = wm + mt * 16 + arow;
                uint32_t off = (uint32_t)(rr * 64 +
                               (((2 * ks + acolg) ^ ((rr >> 1) & 3)) << 4));
                ldsm_x4(ar[mt], aS + off);
            }
#pragma unroll
            for (int np = 0; np < 4; np++) {
                int rr = wn + np * 16 + brow;
                uint32_t boff = (uint32_t)(rr * 64 +
                                (((2 * ks + bcolg) ^ ((rr >> 1) & 3)) << 4));
                uint32_t bh[4], bl[4];
                ldsm_x4(bh, bH + boff);
                ldsm_x4(bl, bL + boff);
#pragma unroll
                for (int mt = 0; mt < 2; mt++) {
                    mma16816(acc[mt][np * 2 + 0], ar[mt], bh + 0);
                    mma16816(acc[mt][np * 2 + 1], ar[mt], bh + 2);
                    mma16816(acc[mt][np * 2 + 0], ar[mt], bl + 0);
                    mma16816(acc[mt][np * 2 + 1], ar[mt], bl + 2);
                }
            }
        }
        __syncthreads();
    }

    const int quad = lane >> 2;
    const int qi   = lane & 3;
#pragma unroll
    for (int mt = 0; mt < 2; mt++) {
        int r0 = m0 + wm + mt * 16 + quad;
#pragma unroll
        for (int nt = 0; nt < 8; nt++) {
            int cc = n0 + wn + nt * 8 + qi * 2;
            if (r0 < Nn) {
                __nv_bfloat162 v = __floats2bfloat162_rn(acc[mt][nt][0], acc[mt][nt][1]);
                *(__nv_bfloat162*)&g_h[(size_t)r0 * Hh + cc] = v;
            }
            if (r0 + 8 < Nn) {
                __nv_bfloat162 v = __floats2bfloat162_rn(acc[mt][nt][2], acc[mt][nt][3]);
                *(__nv_bfloat162*)&g_h[(size_t)(r0 + 8) * Hh + cc] = v;
            }
        }
    }
}

// ======= fused CSR gather-aggregate + bias + LayerNorm + ReLU (layers 2-4) ==

__global__ void __launch_bounds__(256)
agg_kernel(const float* __restrict__ bias,
           const float* __restrict__ gamma,
           const float* __restrict__ beta) {
    const int grp = threadIdx.x >> 7;
    const int n   = blockIdx.x * 2 + grp;
    const int t   = threadIdx.x & 127;
    const int beg = g_off[n], end = g_off[n + 1];
    const int fo  = t * 4;

    float4 acc = make_float4(0.f, 0.f, 0.f, 0.f);
    int j = beg;
    for (; j + 3 < end; j += 4) {
        int   s0 = g_srcv[j],     s1 = g_srcv[j + 1];
        int   s2 = g_srcv[j + 2], s3 = g_srcv[j + 3];
        float w0 = g_wv[j],       w1 = g_wv[j + 1];
        float w2 = g_wv[j + 2],   w3 = g_wv[j + 3];
        uint2 r0 = *(const uint2*)&g_h[(size_t)s0 * Hh + fo];
        uint2 r1 = *(const uint2*)&g_h[(size_t)s1 * Hh + fo];
        uint2 r2 = *(const uint2*)&g_h[(size_t)s2 * Hh + fo];
        uint2 r3 = *(const uint2*)&g_h[(size_t)s3 * Hh + fo];
        float2 a0 = __bfloat1622float2(*(__nv_bfloat162*)&r0.x);
        float2 b0 = __bfloat1622float2(*(__nv_bfloat162*)&r0.y);
        float2 a1 = __bfloat1622float2(*(__nv_bfloat162*)&r1.x);
        float2 b1 = __bfloat1622float2(*(__nv_bfloat162*)&r1.y);
        float2 a2 = __bfloat1622float2(*(__nv_bfloat162*)&r2.x);
        float2 b2 = __bfloat1622float2(*(__nv_bfloat162*)&r2.y);
        float2 a3 = __bfloat1622float2(*(__nv_bfloat162*)&r3.x);
        float2 b3 = __bfloat1622float2(*(__nv_bfloat162*)&r3.y);
        acc.x = fmaf(w0, a0.x, fmaf(w1, a1.x, fmaf(w2, a2.x, fmaf(w3, a3.x, acc.x))));
        acc.y = fmaf(w0, a0.y, fmaf(w1, a1.y, fmaf(w2, a2.y, fmaf(w3, a3.y, acc.y))));
        acc.z = fmaf(w0, b0.x, fmaf(w1, b1.x, fmaf(w2, b2.x, fmaf(w3, b3.x, acc.z))));
        acc.w = fmaf(w0, b0.y, fmaf(w1, b1.y, fmaf(w2, b2.y, fmaf(w3, b3.y, acc.w))));
    }
    for (; j < end; j++) {
        int   s = g_srcv[j];
        float wv = g_wv[j];
        uint2 rv = *(const uint2*)&g_h[(size_t)s * Hh + fo];
        float2 f0 = __bfloat1622float2(*(__nv_bfloat162*)&rv.x);
        float2 f1 = __bfloat1622float2(*(__nv_bfloat162*)&rv.y);
        acc.x = fmaf(wv, f0.x, acc.x);
        acc.y = fmaf(wv, f0.y, acc.y);
        acc.z = fmaf(wv, f1.x, acc.z);
        acc.w = fmaf(wv, f1.y, acc.w);
    }
    float4 b = *(const float4*)&bias[fo];
    acc.x += b.x; acc.y += b.y; acc.z += b.z; acc.w += b.w;

    float s1 = acc.x + acc.y + acc.z + acc.w;
    float s2 = acc.x * acc.x + acc.y * acc.y + acc.z * acc.z + acc.w * acc.w;
#pragma unroll
    for (int o = 16; o > 0; o >>= 1) {
        s1 += __shfl_xor_sync(0xffffffffu, s1, o);
        s2 += __shfl_xor_sync(0xffffffffu, s2, o);
    }
    __shared__ float sm1[8], sm2[8];
    const int wslot = grp * 4 + ((t >> 5) & 3);
    if ((t & 31) == 0) { sm1[wslot] = s1; sm2[wslot] = s2; }
    __syncthreads();
    float S1 = sm1[grp * 4] + sm1[grp * 4 + 1] + sm1[grp * 4 + 2] + sm1[grp * 4 + 3];
    float S2 = sm2[grp * 4] + sm2[grp * 4 + 1] + sm2[grp * 4 + 2] + sm2[grp * 4 + 3];
    float mu  = S1 * (1.0f / Hh);
    float var = S2 * (1.0f / Hh) - mu * mu;
    float inv = rsqrtf(var + EPSL);

    float4 gm = *(const float4*)&gamma[fo];
    float4 bt = *(const float4*)&beta[fo];
    float2 y0, y1;
    y0.x = fmaxf((acc.x - mu) * inv * gm.x + bt.x, 0.f);
    y0.y = fmaxf((acc.y - mu) * inv * gm.y + bt.y, 0.f);
    y1.x = fmaxf((acc.z - mu) * inv * gm.z + bt.z, 0.f);
    y1.y = fmaxf((acc.w - mu) * inv * gm.w + bt.w, 0.f);

    uint2 hv;
    __nv_bfloat162 h0 = __floats2bfloat162_rn(y0.x, y0.y);
    __nv_bfloat162 h1 = __floats2bfloat162_rn(y1.x, y1.y);
    hv.x = *(unsigned*)&h0;
    hv.y = *(unsigned*)&h1;
    *(uint2*)&g_a[(size_t)n * Hh + fo] = hv;
}

// ================= mean pool + output projection =================

__global__ void pool_kernel() {
    int f = threadIdx.x;
    float s = 0.f;
    for (int n = blockIdx.x; n < Nn; n += gridDim.x)
        s += __bfloat162float(g_a[(size_t)n * Hh + f]);
    atomicAdd(&g_pool[f], s);
}

__global__ void out_kernel(const float* __restrict__ Wout,
                           const float* __restrict__ bout,
                           float* __restrict__ out) {
    __shared__ float sm[NOUT][256];
    int t = threadIdx.x;
    float acc[NOUT];
#pragma unroll
    for (int o = 0; o < NOUT; o++) acc[o] = 0.f;
    for (int f = t; f < Hh; f += 256) {
        float p = g_pool[f] * (1.0f / Nn);
#pragma unroll
        for (int o = 0; o < NOUT; o++)
            acc[o] = fmaf(p, Wout[f * NOUT + o], acc[o]);
    }
#pragma unroll
    for (int o = 0; o < NOUT; o++) sm[o][t] = acc[o];
    __syncthreads();
    for (int st = 128; st > 0; st >>= 1) {
        if (t < st) {
#pragma unroll
            for (int o = 0; o < NOUT; o++) sm[o][t] += sm[o][t + st];
        }
        __syncthreads();
    }
    if (t < NOUT) out[t] = sm[t][0] + bout[t];
}

// ================= launch =================

extern "C" void kernel_launch(void* const* d_in, const int* in_sizes, int n_in,
                              void* d_out, int out_size) {
    const float* x  = (const float*)d_in[0];
    const int*   ei = (const int*)d_in[1];
    const float* W1 = (const float*)d_in[2];  const float* b1 = (const float*)d_in[3];
    const float* W2 = (const float*)d_in[4];  const float* b2 = (const float*)d_in[5];
    const float* W3 = (const float*)d_in[6];  const float* b3 = (const float*)d_in[7];
    const float* W4 = (const float*)d_in[8];  const float* b4 = (const float*)d_in[9];
    const float* gm = (const float*)d_in[10]; const float* bt = (const float*)d_in[11];
    const float* Wo = (const float*)d_in[12]; const float* bo = (const float*)d_in[13];
    float* out = (float*)d_out;

    cudaFuncSetAttribute(mma_gemm, cudaFuncAttributeMaxDynamicSharedMemorySize, GEMM_SMEM);

    wt_cvt_kernel<<<(PREP_TOT + 255) / 256, 256>>>(W1, W2, W3, W4, x);   // 0
    deg_kernel<<<(Ee + 255) / 256, 256>>>(ei);                           // 1
    scan_kernel<<<1, 1024>>>();                                          // 2
    fill_kernel<<<(TOT + 255) / 256, 256>>>(ei);                         // 3

    dim3 ggrid(Hh / BN, NP / BM);   // (4, 157)

    // layer 1: aggregate 128-dim input first (agg commutes with GEMM)
    agg1_kernel<<<(Nn + 7) / 8, 256>>>();                                // 4
    mma_gemm<<<ggrid, 256, GEMM_SMEM>>>(0, DIN, WOFF1);                  // 5 (profiled)
    ln_kernel<<<Nn / 2, 256>>>(b1, gm, bt);                              // 6

    // layers 2-4: transform then fused aggregate+LN
    mma_gemm<<<ggrid, 256, GEMM_SMEM>>>(1, Hh, WOFF2);
    agg_kernel<<<Nn / 2, 256>>>(b2, gm, bt);
    mma_gemm<<<ggrid, 256, GEMM_SMEM>>>(1, Hh, WOFF3);
    agg_kernel<<<Nn / 2, 256>>>(b3, gm, bt);
    mma_gemm<<<ggrid, 256, GEMM_SMEM>>>(1, Hh, WOFF4);
    agg_kernel<<<Nn / 2, 256>>>(b4, gm, bt);

    pool_kernel<<<148, 512>>>();
    out_kernel<<<1, 256>>>(Wo, bo, out);
}

// round 17
// speedup vs baseline: 1.3967x; 1.0352x over previous
#include <cuda_runtime.h>
#include <cuda_bf16.h>
#include <cstdint>

#define Nn   20000
#define NP   20096            // padded rows (157 * 128)
#define Ee   320000
#define DIN  128
#define Hh   512
#define NOUT 7
#define TOT  (Ee + Nn)
#define EPSL 1e-5f

// Wt layout: layer1 [512][128] then layers 2-4 [512][512] (hi and lo arrays)
#define WOFF1 0
#define WOFF2 65536
#define WOFF3 327680
#define WOFF4 589824
#define WTOT  851968

// ---- scratch (no allocs allowed: __device__ globals) ----
__device__ __nv_bfloat16 g_h[(size_t)Nn * Hh];          // GEMM output (bf16)
__device__ __nv_bfloat16 g_a[(size_t)NP * Hh];          // activations (bf16, padded)
__device__ __nv_bfloat16 g_ax[(size_t)NP * DIN];        // layer-1 aggregated input
__device__ float g_deg[Nn];
__device__ float g_dinv[Nn];
__device__ int   g_off[Nn + 1];
__device__ int   g_cur[Nn];
__device__ int   g_srcv[TOT];
__device__ float g_wv[TOT];
__device__ float g_pool[Hh];
__device__ __nv_bfloat16 g_wt_hi[WTOT];
__device__ __nv_bfloat16 g_wt_lo[WTOT];

// ================= helpers =================

__device__ __forceinline__ uint32_t smem_u32(const void* p) {
    uint32_t a;
    asm("{ .reg .u64 t; cvta.to.shared.u64 t, %1; cvt.u32.u64 %0, t; }" : "=r"(a) : "l"(p));
    return a;
}
__device__ __forceinline__ void ldsm_x4(uint32_t* r, uint32_t addr) {
    asm volatile("ldmatrix.sync.aligned.m8n8.x4.shared.b16 {%0,%1,%2,%3}, [%4];"
                 : "=r"(r[0]), "=r"(r[1]), "=r"(r[2]), "=r"(r[3]) : "r"(addr));
}
__device__ __forceinline__ void mma16816(float* d, const uint32_t* a, const uint32_t* b) {
    asm volatile("mma.sync.aligned.m16n8k16.row.col.f32.bf16.bf16.f32 "
                 "{%0,%1,%2,%3}, {%4,%5,%6,%7}, {%8,%9}, {%0,%1,%2,%3};"
                 : "+f"(d[0]), "+f"(d[1]), "+f"(d[2]), "+f"(d[3])
                 : "r"(a[0]), "r"(a[1]), "r"(a[2]), "r"(a[3]), "r"(b[0]), "r"(b[1]));
}
__device__ __forceinline__ void cp16(uint32_t dst, const void* src) {
    asm volatile("cp.async.ca.shared.global [%0], [%1], 16;" :: "r"(dst), "l"(src));
}
__device__ __forceinline__ void cp_commit() {
    asm volatile("cp.async.commit_group;" ::: "memory");
}
template <int N> __device__ __forceinline__ void cp_wait() {
    asm volatile("cp.async.wait_group %0;" :: "n"(N) : "memory");
}
__device__ __forceinline__ void bf8_fma(float* acc, const uint4& rv, float wv) {
    float2 p0 = __bfloat1622float2(*(__nv_bfloat162*)&rv.x);
    float2 p1 = __bfloat1622float2(*(__nv_bfloat162*)&rv.y);
    float2 p2 = __bfloat1622float2(*(__nv_bfloat162*)&rv.z);
    float2 p3 = __bfloat1622float2(*(__nv_bfloat162*)&rv.w);
    acc[0] = fmaf(wv, p0.x, acc[0]); acc[1] = fmaf(wv, p0.y, acc[1]);
    acc[2] = fmaf(wv, p1.x, acc[2]); acc[3] = fmaf(wv, p1.y, acc[3]);
    acc[4] = fmaf(wv, p2.x, acc[4]); acc[5] = fmaf(wv, p2.y, acc[5]);
    acc[6] = fmaf(wv, p3.x, acc[6]); acc[7] = fmaf(wv, p3.y, acc[7]);
}

// ================= graph preprocessing =================

__global__ void deg_kernel(const int* __restrict__ ei) {
    int i = blockIdx.x * blockDim.x + threadIdx.x;
    if (i < Ee) atomicAdd(&g_deg[ei[Ee + i]], 1.0f);
}

// warp-shuffle based scan (+ fused dinv), 1024 threads
__global__ void scan_kernel() {
    __shared__ int wsum[32];
    __shared__ int carry;
    int t = threadIdx.x, lane = t & 31, w = t >> 5;
    if (t == 0) { carry = 0; g_off[0] = 0; }
    __syncthreads();
    for (int base = 0; base < Nn; base += 1024) {
        int i = base + t;
        int v = 0;
        if (i < Nn) {
            v = (int)g_deg[i] + 1;
            g_dinv[i] = rsqrtf((float)v);
        }
        int s = v;
#pragma unroll
        for (int o = 1; o < 32; o <<= 1) {
            int u = __shfl_up_sync(0xffffffffu, s, o);
            if (lane >= o) s += u;
        }
        if (lane == 31) wsum[w] = s;
        __syncthreads();
        if (w == 0) {
            int ws = wsum[lane];
#pragma unroll
            for (int o = 1; o < 32; o <<= 1) {
                int u = __shfl_up_sync(0xffffffffu, ws, o);
                if (lane >= o) ws += u;
            }
            wsum[lane] = ws;
        }
        __syncthreads();
        int boff = (w ? wsum[w - 1] : 0);
        if (i < Nn) g_off[i + 1] = carry + boff + s;
        __syncthreads();
        if (t == 0) carry += wsum[31];
        __syncthreads();
    }
}

__global__ void fill_kernel(const int* __restrict__ ei) {
    int i = blockIdx.x * blockDim.x + threadIdx.x;
    if (i >= TOT) return;
    int s, d;
    if (i < Ee) { s = ei[i]; d = ei[Ee + i]; }
    else        { s = i - Ee; d = s; }
    int pos = atomicAdd(&g_cur[d], 1);
    int idx = g_off[d] + pos;
    g_srcv[idx] = s;
    g_wv[idx]   = g_dinv[s] * g_dinv[d];
}

// == fused: weight transpose/split + layer-1 input cvt + scratch zeroing ==

#define CVT_ITEMS (Nn * DIN / 2)
#define PREP_TOT  (WTOT + CVT_ITEMS + Nn)

__global__ void wt_cvt_kernel(const float* __restrict__ W1, const float* __restrict__ W2,
                              const float* __restrict__ W3, const float* __restrict__ W4,
                              const float* __restrict__ x) {
    int idx = blockIdx.x * blockDim.x + threadIdx.x;
    if (idx < WTOT) {
        const float* W; int K, loc;
        if (idx < WOFF2)      { W = W1; K = DIN; loc = idx; }
        else if (idx < WOFF3) { W = W2; K = Hh;  loc = idx - WOFF2; }
        else if (idx < WOFF4) { W = W3; K = Hh;  loc = idx - WOFF3; }
        else                  { W = W4; K = Hh;  loc = idx - WOFF4; }
        int n = loc / K, k = loc % K;          // output index [n][k]
        float a = W[(size_t)k * Hh + n];       // source [k][n]
        __nv_bfloat16 h = __float2bfloat16(a);
        g_wt_hi[idx] = h;
        g_wt_lo[idx] = __float2bfloat16(a - __bfloat162float(h));
    } else if (idx < WTOT + CVT_ITEMS) {
        int i = idx - WTOT;
        float2 v = *(const float2*)&x[i * 2];
        __nv_bfloat162 hv = __floats2bfloat162_rn(v.x, v.y);
        *(__nv_bfloat162*)&g_a[i * 2] = hv;    // layer-1 x as dense [Nn,128] in g_a
    } else {
        int i = idx - WTOT - CVT_ITEMS;   // 0..Nn-1: zero scratch
        g_deg[i] = 0.f;
        g_cur[i] = 0;
        if (i < Hh) g_pool[i] = 0.f;
    }
}

// ===== layer-1 aggregation on 128-dim input (aggregate-before-transform) ====
// one warp per node; lane covers 4 dims (uint2). 8 nodes / 256-thread block.

__global__ void __launch_bounds__(256)
agg1_kernel() {
    const int wrp  = threadIdx.x >> 5;
    const int lane = threadIdx.x & 31;
    const int n    = blockIdx.x * 8 + wrp;
    if (n >= Nn) return;
    const int beg = g_off[n], end = g_off[n + 1];
    const int fo  = lane * 4;

    float4 acc = make_float4(0.f, 0.f, 0.f, 0.f);
    int j = beg;
    for (; j + 1 < end; j += 2) {
        int   s0 = g_srcv[j],   s1 = g_srcv[j + 1];
        float w0 = g_wv[j],     w1 = g_wv[j + 1];
        uint2 r0 = *(const uint2*)&g_a[(size_t)s0 * DIN + fo];
        uint2 r1 = *(const uint2*)&g_a[(size_t)s1 * DIN + fo];
        float2 a0 = __bfloat1622float2(*(__nv_bfloat162*)&r0.x);
        float2 b0 = __bfloat1622float2(*(__nv_bfloat162*)&r0.y);
        float2 a1 = __bfloat1622float2(*(__nv_bfloat162*)&r1.x);
        float2 b1 = __bfloat1622float2(*(__nv_bfloat162*)&r1.y);
        acc.x = fmaf(w0, a0.x, fmaf(w1, a1.x, acc.x));
        acc.y = fmaf(w0, a0.y, fmaf(w1, a1.y, acc.y));
        acc.z = fmaf(w0, b0.x, fmaf(w1, b1.x, acc.z));
        acc.w = fmaf(w0, b0.y, fmaf(w1, b1.y, acc.w));
    }
    if (j < end) {
        int   s = g_srcv[j];
        float wv = g_wv[j];
        uint2 rv = *(const uint2*)&g_a[(size_t)s * DIN + fo];
        float2 f0 = __bfloat1622float2(*(__nv_bfloat162*)&rv.x);
        float2 f1 = __bfloat1622float2(*(__nv_bfloat162*)&rv.y);
        acc.x = fmaf(wv, f0.x, acc.x);
        acc.y = fmaf(wv, f0.y, acc.y);
        acc.z = fmaf(wv, f1.x, acc.z);
        acc.w = fmaf(wv, f1.y, acc.w);
    }
    uint2 hv;
    __nv_bfloat162 h0 = __floats2bfloat162_rn(acc.x, acc.y);
    __nv_bfloat162 h1 = __floats2bfloat162_rn(acc.z, acc.w);
    hv.x = *(unsigned*)&h0;
    hv.y = *(unsigned*)&h1;
    *(uint2*)&g_ax[(size_t)n * DIN + fo] = hv;
}

// ====== layer-1 bias + LayerNorm + ReLU (no gather): g_h -> g_a [Nn,512] ====

__global__ void __launch_bounds__(256)
ln_kernel(const float* __restrict__ bias,
          const float* __restrict__ gamma,
          const float* __restrict__ beta) {
    const int grp = threadIdx.x >> 7;
    const int n   = blockIdx.x * 2 + grp;
    const int t   = threadIdx.x & 127;
    const int fo  = t * 4;

    uint2 rv = *(const uint2*)&g_h[(size_t)n * Hh + fo];
    float2 f0 = __bfloat1622float2(*(__nv_bfloat162*)&rv.x);
    float2 f1 = __bfloat1622float2(*(__nv_bfloat162*)&rv.y);
    float4 b = *(const float4*)&bias[fo];
    float4 acc = make_float4(f0.x + b.x, f0.y + b.y, f1.x + b.z, f1.y + b.w);

    float s1 = acc.x + acc.y + acc.z + acc.w;
    float s2 = acc.x * acc.x + acc.y * acc.y + acc.z * acc.z + acc.w * acc.w;
#pragma unroll
    for (int o = 16; o > 0; o >>= 1) {
        s1 += __shfl_xor_sync(0xffffffffu, s1, o);
        s2 += __shfl_xor_sync(0xffffffffu, s2, o);
    }
    __shared__ float sm1[8], sm2[8];
    const int wslot = grp * 4 + ((t >> 5) & 3);
    if ((t & 31) == 0) { sm1[wslot] = s1; sm2[wslot] = s2; }
    __syncthreads();
    float S1 = sm1[grp * 4] + sm1[grp * 4 + 1] + sm1[grp * 4 + 2] + sm1[grp * 4 + 3];
    float S2 = sm2[grp * 4] + sm2[grp * 4 + 1] + sm2[grp * 4 + 2] + sm2[grp * 4 + 3];
    float mu  = S1 * (1.0f / Hh);
    float var = S2 * (1.0f / Hh) - mu * mu;
    float inv = rsqrtf(var + EPSL);

    float4 gm = *(const float4*)&gamma[fo];
    float4 bt = *(const float4*)&beta[fo];
    float2 y0, y1;
    y0.x = fmaxf((acc.x - mu) * inv * gm.x + bt.x, 0.f);
    y0.y = fmaxf((acc.y - mu) * inv * gm.y + bt.y, 0.f);
    y1.x = fmaxf((acc.z - mu) * inv * gm.z + bt.z, 0.f);
    y1.y = fmaxf((acc.w - mu) * inv * gm.w + bt.w, 0.f);

    uint2 hv;
    __nv_bfloat162 h0 = __floats2bfloat162_rn(y0.x, y0.y);
    __nv_bfloat162 h1 = __floats2bfloat162_rn(y1.x, y1.y);
    hv.x = *(unsigned*)&h0;
    hv.y = *(unsigned*)&h1;
    *(uint2*)&g_a[(size_t)n * Hh + fo] = hv;
}

// ======= warp-MMA bf16 GEMM (weights hi/lo compensated), 2-stage cp.async ====
// asel: 0 -> A = g_ax (K=128), 1 -> A = g_a (K=512). Resolved in device code.

#define BM 128
#define BN 128
#define ARR_B 8192               // bytes per array per stage (128 rows x 64 B)
#define STG_B (3 * ARR_B)        // 24576 per stage (A, BH, BL)
#define GEMM_SMEM (2 * STG_B)    // 49152

__global__ void __launch_bounds__(256, 2)
mma_gemm(int asel, int K, int woff) {
    extern __shared__ __align__(16) char dynsmem[];
    const uint32_t sb = smem_u32(dynsmem);

    const int t    = threadIdx.x;
    const int lane = t & 31;
    const int wid  = t >> 5;
    const int wm   = (wid & 3) * 32;
    const int wn   = (wid >> 2) * 64;
    const int m0   = blockIdx.y * BM;
    const int n0   = blockIdx.x * BN;

    const __nv_bfloat16* Abase = asel ? g_a : g_ax;   // device-side symbol resolution
    const __nv_bfloat16* srcp[3] = {
        Abase + (size_t)m0 * K,
        g_wt_hi + woff + (size_t)n0 * K,
        g_wt_lo + woff + (size_t)n0 * K
    };

    float acc[2][8][4];
#pragma unroll
    for (int i = 0; i < 2; i++)
#pragma unroll
        for (int j = 0; j < 8; j++)
#pragma unroll
            for (int k = 0; k < 4; k++) acc[i][j][k] = 0.f;

    const int nch = K >> 5;

    auto issue = [&](int c) {
        const uint32_t stb = sb + (uint32_t)(c & 1) * STG_B;
        const int k0 = c << 5;
#pragma unroll
        for (int i = 0; i < 6; i++) {
            int seg = t + i * 256;
            int arr = seg >> 9;
            int rem = seg & 511;
            int r   = rem >> 2;
            int sgi = rem & 3;
            uint32_t dst = stb + (uint32_t)(arr * ARR_B + r * 64 +
                                            ((sgi ^ ((r >> 1) & 3)) << 4));
            cp16(dst, srcp[arr] + (size_t)r * K + k0 + sgi * 8);
        }
        cp_commit();
    };

    const int arow = lane & 15, acolg = lane >> 4;
    const int brow = (lane & 7) + ((lane >> 4) << 3);
    const int bcolg = (lane >> 3) & 1;

    issue(0);

    for (int c = 0; c < nch; c++) {
        if (c + 1 < nch) { issue(c + 1); cp_wait<1>(); }
        else             { cp_wait<0>(); }
        __syncthreads();

        const uint32_t stb = sb + (uint32_t)(c & 1) * STG_B;
        const uint32_t aS = stb;
        const uint32_t bH = stb + ARR_B;
        const uint32_t bL = stb + 2 * ARR_B;

#pragma unroll
        for (int ks = 0; ks < 2; ks++) {
            uint32_t ar[2][4];
#pragma unroll
            for (int mt = 0; mt < 2; mt++) {
                int rr = wm + mt * 16 + arow;
                uint32_t off = (uint32_t)(rr * 64 +
                               (((2 * ks + acolg) ^ ((rr >> 1) & 3)) << 4));
                ldsm_x4(ar[mt], aS + off);
            }
#pragma unroll
            for (int np = 0; np < 4; np++) {
                int rr = wn + np * 16 + brow;
                uint32_t boff = (uint32_t)(rr * 64 +
                                (((2 * ks + bcolg) ^ ((rr >> 1) & 3)) << 4));
                uint32_t bh[4], bl[4];
                ldsm_x4(bh, bH + boff);
                ldsm_x4(bl, bL + boff);
#pragma unroll
                for (int mt = 0; mt < 2; mt++) {
                    mma16816(acc[mt][np * 2 + 0], ar[mt], bh + 0);
                    mma16816(acc[mt][np * 2 + 1], ar[mt], bh + 2);
                    mma16816(acc[mt][np * 2 + 0], ar[mt], bl + 0);
                    mma16816(acc[mt][np * 2 + 1], ar[mt], bl + 2);
                }
            }
        }
        __syncthreads();
    }

    const int quad = lane >> 2;
    const int qi   = lane & 3;
#pragma unroll
    for (int mt = 0; mt < 2; mt++) {
        int r0 = m0 + wm + mt * 16 + quad;
#pragma unroll
        for (int nt = 0; nt < 8; nt++) {
            int cc = n0 + wn + nt * 8 + qi * 2;
            if (r0 < Nn) {
                __nv_bfloat162 v = __floats2bfloat162_rn(acc[mt][nt][0], acc[mt][nt][1]);
                *(__nv_bfloat162*)&g_h[(size_t)r0 * Hh + cc] = v;
            }
            if (r0 + 8 < Nn) {
                __nv_bfloat162 v = __floats2bfloat162_rn(acc[mt][nt][2], acc[mt][nt][3]);
                *(__nv_bfloat162*)&g_h[(size_t)(r0 + 8) * Hh + cc] = v;
            }
        }
    }
}

// ======= fused CSR gather-aggregate + bias + LayerNorm + ReLU (layers 2-4) ==
// 4 nodes per 256-thread block; 64 threads per node; uint4 (16B) loads.

__global__ void __launch_bounds__(256)
agg_kernel(const float* __restrict__ bias,
           const float* __restrict__ gamma,
           const float* __restrict__ beta) {
    const int grp = threadIdx.x >> 6;            // 0..3: node within block
    const int n   = blockIdx.x * 4 + grp;
    const int t   = threadIdx.x & 63;            // 64 threads per node
    const int beg = g_off[n], end = g_off[n + 1];
    const int fo  = t * 8;                       // 8 bf16 per thread

    float acc[8];
#pragma unroll
    for (int i = 0; i < 8; i++) acc[i] = 0.f;

    int j = beg;
    for (; j + 1 < end; j += 2) {
        int   s0 = g_srcv[j],   s1 = g_srcv[j + 1];
        float w0 = g_wv[j],     w1 = g_wv[j + 1];
        uint4 r0 = *(const uint4*)&g_h[(size_t)s0 * Hh + fo];
        uint4 r1 = *(const uint4*)&g_h[(size_t)s1 * Hh + fo];
        bf8_fma(acc, r0, w0);
        bf8_fma(acc, r1, w1);
    }
    if (j < end) {
        uint4 rv = *(const uint4*)&g_h[(size_t)g_srcv[j] * Hh + fo];
        bf8_fma(acc, rv, g_wv[j]);
    }

    float4 b0 = *(const float4*)&bias[fo];
    float4 b1 = *(const float4*)&bias[fo + 4];
    acc[0] += b0.x; acc[1] += b0.y; acc[2] += b0.z; acc[3] += b0.w;
    acc[4] += b1.x; acc[5] += b1.y; acc[6] += b1.z; acc[7] += b1.w;

    float s1 = 0.f, s2 = 0.f;
#pragma unroll
    for (int i = 0; i < 8; i++) { s1 += acc[i]; s2 += acc[i] * acc[i]; }
#pragma unroll
    for (int o = 16; o > 0; o >>= 1) {
        s1 += __shfl_xor_sync(0xffffffffu, s1, o);
        s2 += __shfl_xor_sync(0xffffffffu, s2, o);
    }
    __shared__ float sm1[8], sm2[8];
    const int wslot = grp * 2 + ((t >> 5) & 1);  // 2 warps per node
    if ((t & 31) == 0) { sm1[wslot] = s1; sm2[wslot] = s2; }
    __syncthreads();
    float S1 = sm1[grp * 2] + sm1[grp * 2 + 1];
    float S2 = sm2[grp * 2] + sm2[grp * 2 + 1];
    float mu  = S1 * (1.0f / Hh);
    float var = S2 * (1.0f / Hh) - mu * mu;
    float inv = rsqrtf(var + EPSL);

    float4 g0 = *(const float4*)&gamma[fo];
    float4 g1 = *(const float4*)&gamma[fo + 4];
    float4 t0 = *(const float4*)&beta[fo];
    float4 t1 = *(const float4*)&beta[fo + 4];
    float gmv[8] = {g0.x, g0.y, g0.z, g0.w, g1.x, g1.y, g1.z, g1.w};
    float btv[8] = {t0.x, t0.y, t0.z, t0.w, t1.x, t1.y, t1.z, t1.w};

    float y[8];
#pragma unroll
    for (int i = 0; i < 8; i++)
        y[i] = fmaxf((acc[i] - mu) * inv * gmv[i] + btv[i], 0.f);

    uint4 hv;
    __nv_bfloat162 h0 = __floats2bfloat162_rn(y[0], y[1]);
    __nv_bfloat162 h1 = __floats2bfloat162_rn(y[2], y[3]);
    __nv_bfloat162 h2 = __floats2bfloat162_rn(y[4], y[5]);
    __nv_bfloat162 h3 = __floats2bfloat162_rn(y[6], y[7]);
    hv.x = *(unsigned*)&h0;
    hv.y = *(unsigned*)&h1;
    hv.z = *(unsigned*)&h2;
    hv.w = *(unsigned*)&h3;
    *(uint4*)&g_a[(size_t)n * Hh + fo] = hv;
}

// ================= mean pool + output projection =================

__global__ void pool_kernel() {
    int f = threadIdx.x;
    float s = 0.f;
    for (int n = blockIdx.x; n < Nn; n += gridDim.x)
        s += __bfloat162float(g_a[(size_t)n * Hh + f]);
    atomicAdd(&g_pool[f], s);
}

__global__ void out_kernel(const float* __restrict__ Wout,
                           const float* __restrict__ bout,
                           float* __restrict__ out) {
    __shared__ float sm[NOUT][256];
    int t = threadIdx.x;
    float acc[NOUT];
#pragma unroll
    for (int o = 0; o < NOUT; o++) acc[o] = 0.f;
    for (int f = t; f < Hh; f += 256) {
        float p = g_pool[f] * (1.0f / Nn);
#pragma unroll
        for (int o = 0; o < NOUT; o++)
            acc[o] = fmaf(p, Wout[f * NOUT + o], acc[o]);
    }
#pragma unroll
    for (int o = 0; o < NOUT; o++) sm[o][t] = acc[o];
    __syncthreads();
    for (int st = 128; st > 0; st >>= 1) {
        if (t < st) {
#pragma unroll
            for (int o = 0; o < NOUT; o++) sm[o][t] += sm[o][t + st];
        }
        __syncthreads();
    }
    if (t < NOUT) out[t] = sm[t][0] + bout[t];
}

// ================= launch =================

extern "C" void kernel_launch(void* const* d_in, const int* in_sizes, int n_in,
                              void* d_out, int out_size) {
    const float* x  = (const float*)d_in[0];
    const int*   ei = (const int*)d_in[1];
    const float* W1 = (const float*)d_in[2];  const float* b1 = (const float*)d_in[3];
    const float* W2 = (const float*)d_in[4];  const float* b2 = (const float*)d_in[5];
    const float* W3 = (const float*)d_in[6];  const float* b3 = (const float*)d_in[7];
    const float* W4 = (const float*)d_in[8];  const float* b4 = (const float*)d_in[9];
    const float* gm = (const float*)d_in[10]; const float* bt = (const float*)d_in[11];
    const float* Wo = (const float*)d_in[12]; const float* bo = (const float*)d_in[13];
    float* out = (float*)d_out;

    cudaFuncSetAttribute(mma_gemm, cudaFuncAttributeMaxDynamicSharedMemorySize, GEMM_SMEM);

    wt_cvt_kernel<<<(PREP_TOT + 255) / 256, 256>>>(W1, W2, W3, W4, x);   // 0
    deg_kernel<<<(Ee + 255) / 256, 256>>>(ei);                           // 1
    scan_kernel<<<1, 1024>>>();                                          // 2
    fill_kernel<<<(TOT + 255) / 256, 256>>>(ei);                         // 3

    dim3 ggrid(Hh / BN, NP / BM);   // (4, 157)

    // layer 1: aggregate 128-dim input first (agg commutes with GEMM)
    agg1_kernel<<<(Nn + 7) / 8, 256>>>();                                // 4
    mma_gemm<<<ggrid, 256, GEMM_SMEM>>>(0, DIN, WOFF1);                  // 5
    ln_kernel<<<Nn / 2, 256>>>(b1, gm, bt);                              // 6

    // layers 2-4: transform then fused aggregate+LN
    mma_gemm<<<ggrid, 256, GEMM_SMEM>>>(1, Hh, WOFF2);
    agg_kernel<<<Nn / 4, 256>>>(b2, gm, bt);
    mma_gemm<<<ggrid, 256, GEMM_SMEM>>>(1, Hh, WOFF3);
    agg_kernel<<<Nn / 4, 256>>>(b3, gm, bt);
    mma_gemm<<<ggrid, 256, GEMM_SMEM>>>(1, Hh, WOFF4);
    agg_kernel<<<Nn / 4, 256>>>(b4, gm, bt);

    pool_kernel<<<148, 512>>>();
    out_kernel<<<1, 256>>>(Wo, bo, out);
}